// round 2
// baseline (speedup 1.0000x reference)
#include <cuda_runtime.h>
#include <float.h>

// Problem constants
#define N_   2
#define K_   2048
#define DIN_ 1024
#define H_   16
#define D_   64          // DOUT
#define HD_  1024        // H_*D_

// Scratch (device globals: allocation-free)
__device__ float g_q[(size_t)N_ * H_ * K_ * D_];   // (n,h,k,d) 16MB
__device__ float g_k[(size_t)N_ * H_ * K_ * D_];
__device__ float g_v[(size_t)N_ * H_ * K_ * D_];
__device__ float g_y[(size_t)N_ * K_ * HD_];       // (n,k,h*64+d) 16MB

// ---------------------------------------------------------------------------
// Projection: out[n,h,k,d] = sum_r X[n,k,r] * W[h,r,d] + b[h,d]
// grid (M/64=64, H=16), block 256, tile 64x64, K-step 16, 4x4 per thread
// which: 0->g_q, 1->g_k, 2->g_v
// ---------------------------------------------------------------------------
__global__ __launch_bounds__(256) void proj_kernel(
    const float* __restrict__ X, const float* __restrict__ W,
    const float* __restrict__ bias, int which)
{
    __shared__ float As[16][64];   // As[r][m]  (k-major)
    __shared__ float Bs[16][64];   // Bs[r][d]

    float* out = (which == 0) ? g_q : (which == 1) ? g_k : g_v;

    const int h   = blockIdx.y;
    const int m0  = blockIdx.x * 64;
    const int tid = threadIdx.x;
    const int tx  = tid & 15;
    const int ty  = tid >> 4;

    const float* Xp = X + (size_t)m0 * DIN_;
    const float* Wh = W + (size_t)h * (DIN_ * D_);

    const int lm = tid >> 2;          // 0..63  (X row in tile)
    const int lr = (tid & 3) << 2;    // 0,4,8,12 (X col group)
    const int wr = tid >> 4;          // 0..15 (W row)
    const int wd = (tid & 15) << 2;   // 0..60 (W col group)

    float acc[4][4] = {};

    for (int r0 = 0; r0 < DIN_; r0 += 16) {
        float4 xa = *(const float4*)(Xp + (size_t)lm * DIN_ + r0 + lr);
        float4 wb = *(const float4*)(Wh + (size_t)(r0 + wr) * D_ + wd);
        __syncthreads();
        As[lr + 0][lm] = xa.x;
        As[lr + 1][lm] = xa.y;
        As[lr + 2][lm] = xa.z;
        As[lr + 3][lm] = xa.w;
        *(float4*)&Bs[wr][wd] = wb;
        __syncthreads();
#pragma unroll
        for (int rr = 0; rr < 16; rr++) {
            float a[4], b[4];
            *(float4*)a = *(const float4*)&As[rr][ty << 2];
            *(float4*)b = *(const float4*)&Bs[rr][tx << 2];
#pragma unroll
            for (int ii = 0; ii < 4; ii++)
#pragma unroll
                for (int jj = 0; jj < 4; jj++)
                    acc[ii][jj] = fmaf(a[ii], b[jj], acc[ii][jj]);
        }
    }

    // epilogue: map m -> (n,k); tile never straddles n (2048 % 64 == 0)
    const int n  = m0 >> 11;
    const int k0 = m0 & (K_ - 1);
    float4 bv = *(const float4*)(bias + h * D_ + (tx << 2));
#pragma unroll
    for (int ii = 0; ii < 4; ii++) {
        const int krow = k0 + (ty << 2) + ii;
        float4 o;
        o.x = acc[ii][0] + bv.x;
        o.y = acc[ii][1] + bv.y;
        o.z = acc[ii][2] + bv.z;
        o.w = acc[ii][3] + bv.w;
        *(float4*)(out + ((size_t)(n * H_ + h) * K_ + krow) * D_ + (tx << 2)) = o;
    }
}

// ---------------------------------------------------------------------------
// Flash attention per (n,h): 64 query rows per block, online softmax.
// grid (K/64=32, N*H=32), block 256.
// g_y[n, k, h*64+d] = softmax(QK^T/8 masked) V
// mask is int32 (harness materializes bool as int32): nonzero -> -1e9
// ---------------------------------------------------------------------------
__device__ __forceinline__ float rmax16(float v) {
    v = fmaxf(v, __shfl_xor_sync(0xffffffffu, v, 8, 16));
    v = fmaxf(v, __shfl_xor_sync(0xffffffffu, v, 4, 16));
    v = fmaxf(v, __shfl_xor_sync(0xffffffffu, v, 2, 16));
    v = fmaxf(v, __shfl_xor_sync(0xffffffffu, v, 1, 16));
    return v;
}
__device__ __forceinline__ float rsum16(float v) {
    v += __shfl_xor_sync(0xffffffffu, v, 8, 16);
    v += __shfl_xor_sync(0xffffffffu, v, 4, 16);
    v += __shfl_xor_sync(0xffffffffu, v, 2, 16);
    v += __shfl_xor_sync(0xffffffffu, v, 1, 16);
    return v;
}

__global__ __launch_bounds__(256) void flash_kernel(const int* __restrict__ mask)
{
    __shared__ float Qs[64][64];   // Qs[d][i]  (d-major)
    __shared__ float KPs[64][64];  // phase 1: K[d][j] ; phase 2: P[j][i]
    __shared__ float Vs[64][64];   // Vs[j][d]  (row-major)

    const int qt  = blockIdx.x;    // q tile 0..31
    const int nh  = blockIdx.y;    // 0..31
    const int n   = nh >> 4;
    const int h   = nh & 15;
    const int tid = threadIdx.x;
    const int tx  = tid & 15;
    const int ty  = tid >> 4;

    const float* Qg = g_q + ((size_t)nh * K_ + qt * 64) * D_;
    const float* Kg = g_k + (size_t)nh * K_ * D_;
    const float* Vg = g_v + (size_t)nh * K_ * D_;
    const int* Mg = mask + ((size_t)n * K_ + qt * 64) * K_;

    // load Q tile transposed: Qs[d][i] = Q[i][d]
#pragma unroll
    for (int it = 0; it < 4; it++) {
        const int idx = tid + it * 256;
        const int row = idx >> 4;
        const int c0  = (idx & 15) << 2;
        float4 q4 = *(const float4*)(Qg + (size_t)row * D_ + c0);
        Qs[c0 + 0][row] = q4.x;
        Qs[c0 + 1][row] = q4.y;
        Qs[c0 + 2][row] = q4.z;
        Qs[c0 + 3][row] = q4.w;
    }

    float o[4][4] = {};
    float mrow[4] = {-FLT_MAX, -FLT_MAX, -FLT_MAX, -FLT_MAX};
    float lrow[4] = {};

    for (int t = 0; t < K_ / 64; t++) {
        __syncthreads();   // prior PV reads of KPs/Vs done; Qs stores done (t==0)

        // load K tile transposed + V tile straight
#pragma unroll
        for (int it = 0; it < 4; it++) {
            const int idx = tid + it * 256;
            const int row = idx >> 4;
            const int c0  = (idx & 15) << 2;
            float4 k4 = *(const float4*)(Kg + ((size_t)(t * 64 + row)) * D_ + c0);
            KPs[c0 + 0][row] = k4.x;
            KPs[c0 + 1][row] = k4.y;
            KPs[c0 + 2][row] = k4.z;
            KPs[c0 + 3][row] = k4.w;
            float4 v4 = *(const float4*)(Vg + ((size_t)(t * 64 + row)) * D_ + c0);
            *(float4*)&Vs[row][c0] = v4;
        }
        __syncthreads();

        // S = Q K^T  (64x64x64)
        float s[4][4] = {};
#pragma unroll 16
        for (int d = 0; d < 64; d++) {
            float a[4], b[4];
            *(float4*)a = *(const float4*)&Qs[d][ty << 2];
            *(float4*)b = *(const float4*)&KPs[d][tx << 2];
#pragma unroll
            for (int ii = 0; ii < 4; ii++)
#pragma unroll
                for (int jj = 0; jj < 4; jj++)
                    s[ii][jj] = fmaf(a[ii], b[jj], s[ii][jj]);
        }

        // scale + mask (int32 mask, nonzero -> exactly -1e9, matching reference)
#pragma unroll
        for (int ii = 0; ii < 4; ii++) {
            int4 mv = *(const int4*)(Mg + (size_t)((ty << 2) + ii) * K_ + t * 64 + (tx << 2));
            s[ii][0] = mv.x ? -1e9f : s[ii][0] * 0.125f;
            s[ii][1] = mv.y ? -1e9f : s[ii][1] * 0.125f;
            s[ii][2] = mv.z ? -1e9f : s[ii][2] * 0.125f;
            s[ii][3] = mv.w ? -1e9f : s[ii][3] * 0.125f;
        }

        // online softmax update
#pragma unroll
        for (int ii = 0; ii < 4; ii++) {
            float mx = fmaxf(fmaxf(s[ii][0], s[ii][1]), fmaxf(s[ii][2], s[ii][3]));
            mx = rmax16(mx);
            const float mnew = fmaxf(mrow[ii], mx);
            const float f = __expf(mrow[ii] - mnew);
            mrow[ii] = mnew;
            float sum = 0.f;
#pragma unroll
            for (int jj = 0; jj < 4; jj++) {
                s[ii][jj] = __expf(s[ii][jj] - mnew);
                sum += s[ii][jj];
            }
            sum = rsum16(sum);
            lrow[ii] = lrow[ii] * f + sum;
#pragma unroll
            for (int jj = 0; jj < 4; jj++) o[ii][jj] *= f;
        }

        __syncthreads();   // everyone done reading KPs as K

        // write P transposed into KPs: KPs[j][i]
#pragma unroll
        for (int jj = 0; jj < 4; jj++) {
            float4 pv = make_float4(s[0][jj], s[1][jj], s[2][jj], s[3][jj]);
            *(float4*)&KPs[(tx << 2) + jj][ty << 2] = pv;
        }
        __syncthreads();

        // O += P V  (64x64x64)
#pragma unroll 16
        for (int j = 0; j < 64; j++) {
            float a[4], b[4];
            *(float4*)a = *(const float4*)&KPs[j][ty << 2];
            *(float4*)b = *(const float4*)&Vs[j][tx << 2];
#pragma unroll
            for (int ii = 0; ii < 4; ii++)
#pragma unroll
                for (int jj = 0; jj < 4; jj++)
                    o[ii][jj] = fmaf(a[ii], b[jj], o[ii][jj]);
        }
    }

    // epilogue: y[n, qrow, h*64+d] = o / l  (concat-head layout)
#pragma unroll
    for (int ii = 0; ii < 4; ii++) {
        const float inv = 1.0f / lrow[ii];
        float4 ov = make_float4(o[ii][0] * inv, o[ii][1] * inv,
                                o[ii][2] * inv, o[ii][3] * inv);
        const size_t row = (size_t)n * K_ + qt * 64 + (ty << 2) + ii;
        *(float4*)(g_y + row * HD_ + h * D_ + (tx << 2)) = ov;
    }
}

// ---------------------------------------------------------------------------
// Output projection: out[m, j] = sum_r Y[m,r] * Wp[r,j] + bp[j]
// grid (M/64=64, 1024/64=16), block 256.
// ---------------------------------------------------------------------------
__global__ __launch_bounds__(256) void outproj_kernel(
    const float* __restrict__ Wp, const float* __restrict__ bp,
    float* __restrict__ out)
{
    __shared__ float As[16][64];
    __shared__ float Bs[16][64];

    const int j0  = blockIdx.y * 64;
    const int m0  = blockIdx.x * 64;
    const int tid = threadIdx.x;
    const int tx  = tid & 15;
    const int ty  = tid >> 4;

    const float* Yp = g_y + (size_t)m0 * HD_;

    const int lm = tid >> 2;
    const int lr = (tid & 3) << 2;
    const int wr = tid >> 4;
    const int wd = (tid & 15) << 2;

    float acc[4][4] = {};

    for (int r0 = 0; r0 < HD_; r0 += 16) {
        float4 xa = *(const float4*)(Yp + (size_t)lm * HD_ + r0 + lr);
        float4 wb = *(const float4*)(Wp + (size_t)(r0 + wr) * DIN_ + j0 + wd);
        __syncthreads();
        As[lr + 0][lm] = xa.x;
        As[lr + 1][lm] = xa.y;
        As[lr + 2][lm] = xa.z;
        As[lr + 3][lm] = xa.w;
        *(float4*)&Bs[wr][wd] = wb;
        __syncthreads();
#pragma unroll
        for (int rr = 0; rr < 16; rr++) {
            float a[4], b[4];
            *(float4*)a = *(const float4*)&As[rr][ty << 2];
            *(float4*)b = *(const float4*)&Bs[rr][tx << 2];
#pragma unroll
            for (int ii = 0; ii < 4; ii++)
#pragma unroll
                for (int jj = 0; jj < 4; jj++)
                    acc[ii][jj] = fmaf(a[ii], b[jj], acc[ii][jj]);
        }
    }

    float4 bv = *(const float4*)(bp + j0 + (tx << 2));
#pragma unroll
    for (int ii = 0; ii < 4; ii++) {
        float4 ov;
        ov.x = acc[ii][0] + bv.x;
        ov.y = acc[ii][1] + bv.y;
        ov.z = acc[ii][2] + bv.z;
        ov.w = acc[ii][3] + bv.w;
        *(float4*)(out + (size_t)(m0 + (ty << 2) + ii) * DIN_ + j0 + (tx << 2)) = ov;
    }
}

// ---------------------------------------------------------------------------
extern "C" void kernel_launch(void* const* d_in, const int* in_sizes, int n_in,
                              void* d_out, int out_size)
{
    const float* query = (const float*)d_in[0];
    const float* key   = (const float*)d_in[1];
    const float* value = (const float*)d_in[2];
    const int*   mask  = (const int*)d_in[3];
    const float* Wq = (const float*)d_in[4];
    const float* bq = (const float*)d_in[5];
    const float* Wk = (const float*)d_in[6];
    const float* bk = (const float*)d_in[7];
    const float* Wv = (const float*)d_in[8];
    const float* bv = (const float*)d_in[9];
    const float* Wp = (const float*)d_in[10];
    const float* bp = (const float*)d_in[11];
    float* out = (float*)d_out;

    dim3 blk(256);
    dim3 gproj(64, 16);
    proj_kernel<<<gproj, blk>>>(query, Wq, bq, 0);
    proj_kernel<<<gproj, blk>>>(key,   Wk, bk, 1);
    proj_kernel<<<gproj, blk>>>(value, Wv, bv, 2);

    dim3 gflash(32, 32);
    flash_kernel<<<gflash, blk>>>(mask);

    dim3 gout(64, 16);
    outproj_kernel<<<gout, blk>>>(Wp, bp, out);
}

// round 4
// speedup vs baseline: 1.4557x; 1.4557x over previous
#include <cuda_runtime.h>
#include <cstdint>
#include <float.h>

// Problem constants
#define N_   2
#define K_   2048
#define DIN_ 1024
#define H_   16
#define D_   64          // DOUT
#define HD_  1024        // H_*D_

// Scratch (device globals: allocation-free)
__device__ float g_q[(size_t)N_ * H_ * K_ * D_];   // (n,h,k,d) 16MB
__device__ float g_k[(size_t)N_ * H_ * K_ * D_];
__device__ float g_v[(size_t)N_ * H_ * K_ * D_];
__device__ float g_y[(size_t)N_ * K_ * HD_];       // (n,k,h*64+d) 16MB

__device__ __forceinline__ uint32_t f2tf(float x) {
    uint32_t r;
    asm("cvt.rna.tf32.f32 %0, %1;" : "=r"(r) : "f"(x));
    return r;
}

__device__ __forceinline__ void mma_tf32(float* c, const uint32_t* a, const uint32_t* b) {
    asm volatile(
        "mma.sync.aligned.m16n8k8.row.col.f32.tf32.tf32.f32 "
        "{%0,%1,%2,%3}, {%4,%5,%6,%7}, {%8,%9}, {%0,%1,%2,%3};"
        : "+f"(c[0]), "+f"(c[1]), "+f"(c[2]), "+f"(c[3])
        : "r"(a[0]), "r"(a[1]), "r"(a[2]), "r"(a[3]), "r"(b[0]), "r"(b[1]));
}

// ===========================================================================
// tf32 mma.sync GEMM: C(4096 x 1024) = A(4096x1024) @ B + bias
// grid (32 M-tiles, 8 N-tiles), block 256 (8 warps: 2m x 4n, warp tile 64x32)
// B element (k, nglob): addr = B + k*ldb + (nglob & n_mask) + (nglob>>6)*hs
//   proj:    ldb=64,   n_mask=63,   hs=65536  (W is (H,1024,64))
//   outproj: ldb=1024, n_mask=1023, hs=0
// which: 0->g_q 1->g_k 2->g_v (proj (n,h,k,d) layout), 3->Cflat row-major
// ===========================================================================
__global__ __launch_bounds__(256) void gemm_mma(
    const float* __restrict__ Ain, const float* __restrict__ B,
    const float* __restrict__ bias, float* __restrict__ Cflat,
    int ldb, int n_mask, int hs, int which)
{
    __shared__ uint32_t As[2][128][20];   // row-major A tile, stride 20 (16+4 pad)
    __shared__ uint32_t Bs[2][16][136];   // k-major B tile, stride 136 (128+8 pad)

    const int tid  = threadIdx.x;
    const int wid  = tid >> 5;
    const int lane = tid & 31;
    const int gid  = lane >> 2;       // 0..7
    const int tig  = lane & 3;        // 0..3
    const int wm   = wid >> 2;        // 0..1 (64-row half)
    const int wn   = wid & 3;         // 0..3 (32-col quarter)

    const int m0 = blockIdx.x * 128;
    const int by = blockIdx.y;

    const float* A = (which == 3) ? g_y : Ain;

    // LDG mappings
    const int am  = tid >> 2;         // A row within tile (0..63, +64 on iter 1)
    const int akg = tid & 3;          // A k-group (4 floats)
    const int bk  = tid >> 5;         // B k row (0..7, +8 on iter 1)
    const int bn4 = (tid & 31) << 2;  // B n group (4 floats)

    float acc[4][4][4] = {};

    float4 av[2], bvv[2];

    // ---- prologue: load chunk 0 ----
#pragma unroll
    for (int i = 0; i < 2; i++) {
        av[i]  = *(const float4*)(A + (size_t)(m0 + am + i * 64) * DIN_ + akg * 4);
        const int ng = by * 128 + bn4;
        bvv[i] = *(const float4*)(B + (size_t)(bk + i * 8) * ldb +
                                  (ng & n_mask) + (size_t)(ng >> 6) * hs);
    }
#pragma unroll
    for (int i = 0; i < 2; i++) {
        uint32_t* ap = &As[0][am + i * 64][akg * 4];
        ap[0] = f2tf(av[i].x); ap[1] = f2tf(av[i].y);
        ap[2] = f2tf(av[i].z); ap[3] = f2tf(av[i].w);
        uint32_t* bp = &Bs[0][bk + i * 8][bn4];
        bp[0] = f2tf(bvv[i].x); bp[1] = f2tf(bvv[i].y);
        bp[2] = f2tf(bvv[i].z); bp[3] = f2tf(bvv[i].w);
    }
    __syncthreads();

    for (int c = 0; c < DIN_ / 16; c++) {
        const int buf = c & 1;

        // prefetch next chunk into registers (overlaps with MMA below)
        if (c < DIN_ / 16 - 1) {
            const int kc = (c + 1) * 16;
#pragma unroll
            for (int i = 0; i < 2; i++) {
                av[i]  = *(const float4*)(A + (size_t)(m0 + am + i * 64) * DIN_ + kc + akg * 4);
                const int ng = by * 128 + bn4;
                bvv[i] = *(const float4*)(B + (size_t)(kc + bk + i * 8) * ldb +
                                          (ng & n_mask) + (size_t)(ng >> 6) * hs);
            }
        }

        // ---- MMA over this 16-deep chunk (two k8 steps) ----
#pragma unroll
        for (int ks = 0; ks < 16; ks += 8) {
            uint32_t afr[4][4];
#pragma unroll
            for (int mt = 0; mt < 4; mt++) {
                const int mr = wm * 64 + mt * 16;
                afr[mt][0] = As[buf][mr + gid][ks + tig];
                afr[mt][1] = As[buf][mr + gid + 8][ks + tig];
                afr[mt][2] = As[buf][mr + gid][ks + tig + 4];
                afr[mt][3] = As[buf][mr + gid + 8][ks + tig + 4];
            }
            uint32_t bfr[4][2];
#pragma unroll
            for (int nt = 0; nt < 4; nt++) {
                const int nc = wn * 32 + nt * 8 + gid;
                bfr[nt][0] = Bs[buf][ks + tig][nc];
                bfr[nt][1] = Bs[buf][ks + tig + 4][nc];
            }
#pragma unroll
            for (int mt = 0; mt < 4; mt++)
#pragma unroll
                for (int nt = 0; nt < 4; nt++)
                    mma_tf32(acc[mt][nt], afr[mt], bfr[nt]);
        }

        // ---- store prefetched chunk into other buffer ----
        if (c < DIN_ / 16 - 1) {
#pragma unroll
            for (int i = 0; i < 2; i++) {
                uint32_t* ap = &As[buf ^ 1][am + i * 64][akg * 4];
                ap[0] = f2tf(av[i].x); ap[1] = f2tf(av[i].y);
                ap[2] = f2tf(av[i].z); ap[3] = f2tf(av[i].w);
                uint32_t* bp = &Bs[buf ^ 1][bk + i * 8][bn4];
                bp[0] = f2tf(bvv[i].x); bp[1] = f2tf(bvv[i].y);
                bp[2] = f2tf(bvv[i].z); bp[3] = f2tf(bvv[i].w);
            }
            __syncthreads();
        }
    }

    // ---- epilogue: bias + store ----
    float* proj_out = (which == 0) ? g_q : (which == 1) ? g_k : g_v;
#pragma unroll
    for (int mt = 0; mt < 4; mt++) {
#pragma unroll
        for (int nt = 0; nt < 4; nt++) {
            const int cc = wn * 32 + nt * 8 + 2 * tig;   // col within 128-tile
            const int ng = by * 128 + cc;                // global col 0..1023
            const float b0 = bias[ng], b1 = bias[ng + 1];
#pragma unroll
            for (int half = 0; half < 2; half++) {
                const int m = m0 + wm * 64 + mt * 16 + gid + half * 8;
                float2 o;
                o.x = acc[mt][nt][half * 2 + 0] + b0;
                o.y = acc[mt][nt][half * 2 + 1] + b1;
                if (which != 3) {
                    const int nn = m >> 11;
                    const int kk = m & (K_ - 1);
                    const int h  = ng >> 6;
                    const int d  = ng & 63;
                    *(float2*)(proj_out + (((size_t)(nn * H_ + h) * K_ + kk) * D_ + d)) = o;
                } else {
                    *(float2*)(Cflat + (size_t)m * HD_ + ng) = o;
                }
            }
        }
    }
}

// ===========================================================================
// Flash attention (unchanged — SIMT fp32, passing)
// ===========================================================================
__device__ __forceinline__ float rmax16(float v) {
    v = fmaxf(v, __shfl_xor_sync(0xffffffffu, v, 8, 16));
    v = fmaxf(v, __shfl_xor_sync(0xffffffffu, v, 4, 16));
    v = fmaxf(v, __shfl_xor_sync(0xffffffffu, v, 2, 16));
    v = fmaxf(v, __shfl_xor_sync(0xffffffffu, v, 1, 16));
    return v;
}
__device__ __forceinline__ float rsum16(float v) {
    v += __shfl_xor_sync(0xffffffffu, v, 8, 16);
    v += __shfl_xor_sync(0xffffffffu, v, 4, 16);
    v += __shfl_xor_sync(0xffffffffu, v, 2, 16);
    v += __shfl_xor_sync(0xffffffffu, v, 1, 16);
    return v;
}

__global__ __launch_bounds__(256) void flash_kernel(const int* __restrict__ mask)
{
    __shared__ float Qs[64][64];
    __shared__ float KPs[64][64];
    __shared__ float Vs[64][64];

    const int qt  = blockIdx.x;
    const int nh  = blockIdx.y;
    const int n   = nh >> 4;
    const int h   = nh & 15;
    const int tid = threadIdx.x;
    const int tx  = tid & 15;
    const int ty  = tid >> 4;

    const float* Qg = g_q + ((size_t)nh * K_ + qt * 64) * D_;
    const float* Kg = g_k + (size_t)nh * K_ * D_;
    const float* Vg = g_v + (size_t)nh * K_ * D_;
    const int* Mg = mask + ((size_t)n * K_ + qt * 64) * K_;

#pragma unroll
    for (int it = 0; it < 4; it++) {
        const int idx = tid + it * 256;
        const int row = idx >> 4;
        const int c0  = (idx & 15) << 2;
        float4 q4 = *(const float4*)(Qg + (size_t)row * D_ + c0);
        Qs[c0 + 0][row] = q4.x;
        Qs[c0 + 1][row] = q4.y;
        Qs[c0 + 2][row] = q4.z;
        Qs[c0 + 3][row] = q4.w;
    }

    float o[4][4] = {};
    float mrow[4] = {-FLT_MAX, -FLT_MAX, -FLT_MAX, -FLT_MAX};
    float lrow[4] = {};

    for (int t = 0; t < K_ / 64; t++) {
        __syncthreads();

#pragma unroll
        for (int it = 0; it < 4; it++) {
            const int idx = tid + it * 256;
            const int row = idx >> 4;
            const int c0  = (idx & 15) << 2;
            float4 k4 = *(const float4*)(Kg + ((size_t)(t * 64 + row)) * D_ + c0);
            KPs[c0 + 0][row] = k4.x;
            KPs[c0 + 1][row] = k4.y;
            KPs[c0 + 2][row] = k4.z;
            KPs[c0 + 3][row] = k4.w;
            float4 v4 = *(const float4*)(Vg + ((size_t)(t * 64 + row)) * D_ + c0);
            *(float4*)&Vs[row][c0] = v4;
        }
        __syncthreads();

        float s[4][4] = {};
#pragma unroll 16
        for (int d = 0; d < 64; d++) {
            float a[4], b[4];
            *(float4*)a = *(const float4*)&Qs[d][ty << 2];
            *(float4*)b = *(const float4*)&KPs[d][tx << 2];
#pragma unroll
            for (int ii = 0; ii < 4; ii++)
#pragma unroll
                for (int jj = 0; jj < 4; jj++)
                    s[ii][jj] = fmaf(a[ii], b[jj], s[ii][jj]);
        }

#pragma unroll
        for (int ii = 0; ii < 4; ii++) {
            int4 mv = *(const int4*)(Mg + (size_t)((ty << 2) + ii) * K_ + t * 64 + (tx << 2));
            s[ii][0] = mv.x ? -1e9f : s[ii][0] * 0.125f;
            s[ii][1] = mv.y ? -1e9f : s[ii][1] * 0.125f;
            s[ii][2] = mv.z ? -1e9f : s[ii][2] * 0.125f;
            s[ii][3] = mv.w ? -1e9f : s[ii][3] * 0.125f;
        }

#pragma unroll
        for (int ii = 0; ii < 4; ii++) {
            float mx = fmaxf(fmaxf(s[ii][0], s[ii][1]), fmaxf(s[ii][2], s[ii][3]));
            mx = rmax16(mx);
            const float mnew = fmaxf(mrow[ii], mx);
            const float f = __expf(mrow[ii] - mnew);
            mrow[ii] = mnew;
            float sum = 0.f;
#pragma unroll
            for (int jj = 0; jj < 4; jj++) {
                s[ii][jj] = __expf(s[ii][jj] - mnew);
                sum += s[ii][jj];
            }
            sum = rsum16(sum);
            lrow[ii] = lrow[ii] * f + sum;
#pragma unroll
            for (int jj = 0; jj < 4; jj++) o[ii][jj] *= f;
        }

        __syncthreads();

#pragma unroll
        for (int jj = 0; jj < 4; jj++) {
            float4 pv = make_float4(s[0][jj], s[1][jj], s[2][jj], s[3][jj]);
            *(float4*)&KPs[(tx << 2) + jj][ty << 2] = pv;
        }
        __syncthreads();

#pragma unroll 16
        for (int j = 0; j < 64; j++) {
            float a[4], b[4];
            *(float4*)a = *(const float4*)&KPs[j][ty << 2];
            *(float4*)b = *(const float4*)&Vs[j][tx << 2];
#pragma unroll
            for (int ii = 0; ii < 4; ii++)
#pragma unroll
                for (int jj = 0; jj < 4; jj++)
                    o[ii][jj] = fmaf(a[ii], b[jj], o[ii][jj]);
        }
    }

#pragma unroll
    for (int ii = 0; ii < 4; ii++) {
        const float inv = 1.0f / lrow[ii];
        float4 ov = make_float4(o[ii][0] * inv, o[ii][1] * inv,
                                o[ii][2] * inv, o[ii][3] * inv);
        const size_t row = (size_t)n * K_ + qt * 64 + (ty << 2) + ii;
        *(float4*)(g_y + row * HD_ + h * D_ + (tx << 2)) = ov;
    }
}

// ===========================================================================
extern "C" void kernel_launch(void* const* d_in, const int* in_sizes, int n_in,
                              void* d_out, int out_size)
{
    const float* query = (const float*)d_in[0];
    const float* key   = (const float*)d_in[1];
    const float* value = (const float*)d_in[2];
    const int*   mask  = (const int*)d_in[3];
    const float* Wq = (const float*)d_in[4];
    const float* bq = (const float*)d_in[5];
    const float* Wk = (const float*)d_in[6];
    const float* bk = (const float*)d_in[7];
    const float* Wv = (const float*)d_in[8];
    const float* bv = (const float*)d_in[9];
    const float* Wp = (const float*)d_in[10];
    const float* bp = (const float*)d_in[11];
    float* out = (float*)d_out;

    dim3 gg(32, 8), gb(256);
    gemm_mma<<<gg, gb>>>(query, Wq, bq, nullptr, 64, 63, 65536, 0);
    gemm_mma<<<gg, gb>>>(key,   Wk, bk, nullptr, 64, 63, 65536, 1);
    gemm_mma<<<gg, gb>>>(value, Wv, bv, nullptr, 64, 63, 65536, 2);

    dim3 gflash(32, 32), blk(256);
    flash_kernel<<<gflash, blk>>>(mask);

    gemm_mma<<<gg, gb>>>(nullptr, Wp, bp, out, 1024, 1023, 0, 3);
}

// round 5
// speedup vs baseline: 1.5208x; 1.0447x over previous
#include <cuda_runtime.h>
#include <cstdint>
#include <float.h>

// Problem constants
#define N_   2
#define K_   2048
#define DIN_ 1024
#define H_   16
#define D_   64          // DOUT
#define HD_  1024        // H_*D_

// Scratch (device globals: allocation-free)
__device__ float g_q[(size_t)N_ * H_ * K_ * D_];   // (n,h,k,d)
__device__ float g_k[(size_t)N_ * H_ * K_ * D_];
__device__ float g_v[(size_t)N_ * H_ * K_ * D_];
__device__ float g_y[(size_t)N_ * K_ * HD_];       // (n,k,h*64+d)
__device__ uint32_t g_mb[(size_t)N_ * K_ * (K_ / 32)];  // packed mask bits, 1MB

__device__ __forceinline__ uint32_t f2tf(float x) {
    uint32_t r;
    asm("cvt.rna.tf32.f32 %0, %1;" : "=r"(r) : "f"(x));
    return r;
}

__device__ __forceinline__ void mma_tf32(float* c, const uint32_t* a, const uint32_t* b) {
    asm volatile(
        "mma.sync.aligned.m16n8k8.row.col.f32.tf32.tf32.f32 "
        "{%0,%1,%2,%3}, {%4,%5,%6,%7}, {%8,%9}, {%0,%1,%2,%3};"
        : "+f"(c[0]), "+f"(c[1]), "+f"(c[2]), "+f"(c[3])
        : "r"(a[0]), "r"(a[1]), "r"(a[2]), "r"(a[3]), "r"(b[0]), "r"(b[1]));
}

// ===========================================================================
// Mask pack: g_mb bit j of word (n*K + i)*64 + j/32  = mask[n,i,j] != 0
// ===========================================================================
__global__ __launch_bounds__(256) void mask_pack(const int* __restrict__ mask)
{
    const int idx = blockIdx.x * 256 + threadIdx.x;
    const int v = mask[idx];
    const uint32_t b = __ballot_sync(0xffffffffu, v != 0);
    if ((threadIdx.x & 31) == 0) g_mb[idx >> 5] = b;
}

// ===========================================================================
// 3xTF32 mma.sync GEMM: C(4096 x 1024) = A(4096x1024) @ B + bias
// grid (32 M-tiles, 8 N-tiles), block 256 (8 warps: 2m x 4n, warp tile 64x32)
// A,B split into tf32 hi/lo; acc = Ah*Bh + Al*Bh + Ah*Bl  (fp32-accurate)
//   proj:    ldb=64,   n_mask=63,   hs=65536  (W is (H,1024,64))
//   outproj: ldb=1024, n_mask=1023, hs=0
// which: 0->g_q 1->g_k 2->g_v (proj (n,h,k,d) layout), 3->Cflat row-major
// ===========================================================================
#define ASM(b,hl,r,c) gsm[(((b)*2+(hl))*128 + (r))*20 + (c)]
#define BSM(b,hl,r,c) gsm[10240 + (((b)*2+(hl))*16 + (r))*136 + (c)]
#define GEMM_SMEM ((10240 + 8704) * 4)

__global__ __launch_bounds__(256) void gemm_mma(
    const float* __restrict__ Ain, const float* __restrict__ B,
    const float* __restrict__ bias, float* __restrict__ Cflat,
    int ldb, int n_mask, int hs, int which)
{
    extern __shared__ uint32_t gsm[];

    const int tid  = threadIdx.x;
    const int wid  = tid >> 5;
    const int lane = tid & 31;
    const int gid  = lane >> 2;
    const int tig  = lane & 3;
    const int wm   = wid >> 2;
    const int wn   = wid & 3;

    const int m0 = blockIdx.x * 128;
    const int by = blockIdx.y;

    const float* A = (which == 3) ? g_y : Ain;

    const int am  = tid >> 2;
    const int akg = tid & 3;
    const int bk  = tid >> 5;
    const int bn4 = (tid & 31) << 2;

    float acc[4][4][4] = {};
    float4 av[2], bvv[2];

    // ---- prologue: load + split chunk 0 ----
#pragma unroll
    for (int i = 0; i < 2; i++) {
        av[i]  = *(const float4*)(A + (size_t)(m0 + am + i * 64) * DIN_ + akg * 4);
        const int ng = by * 128 + bn4;
        bvv[i] = *(const float4*)(B + (size_t)(bk + i * 8) * ldb +
                                  (ng & n_mask) + (size_t)(ng >> 6) * hs);
    }
#pragma unroll
    for (int i = 0; i < 2; i++) {
        const float af[4] = { av[i].x, av[i].y, av[i].z, av[i].w };
        const float bf[4] = { bvv[i].x, bvv[i].y, bvv[i].z, bvv[i].w };
#pragma unroll
        for (int u = 0; u < 4; u++) {
            uint32_t h = f2tf(af[u]);
            ASM(0, 0, am + i * 64, akg * 4 + u) = h;
            ASM(0, 1, am + i * 64, akg * 4 + u) = f2tf(af[u] - __uint_as_float(h));
            uint32_t hb = f2tf(bf[u]);
            BSM(0, 0, bk + i * 8, bn4 + u) = hb;
            BSM(0, 1, bk + i * 8, bn4 + u) = f2tf(bf[u] - __uint_as_float(hb));
        }
    }
    __syncthreads();

    for (int c = 0; c < DIN_ / 16; c++) {
        const int buf = c & 1;

        if (c < DIN_ / 16 - 1) {
            const int kc = (c + 1) * 16;
#pragma unroll
            for (int i = 0; i < 2; i++) {
                av[i]  = *(const float4*)(A + (size_t)(m0 + am + i * 64) * DIN_ + kc + akg * 4);
                const int ng = by * 128 + bn4;
                bvv[i] = *(const float4*)(B + (size_t)(kc + bk + i * 8) * ldb +
                                          (ng & n_mask) + (size_t)(ng >> 6) * hs);
            }
        }

#pragma unroll
        for (int ks = 0; ks < 16; ks += 8) {
            uint32_t ah[4][4], al[4][4];
#pragma unroll
            for (int mt = 0; mt < 4; mt++) {
                const int mr = wm * 64 + mt * 16;
                ah[mt][0] = ASM(buf, 0, mr + gid,     ks + tig);
                ah[mt][1] = ASM(buf, 0, mr + gid + 8, ks + tig);
                ah[mt][2] = ASM(buf, 0, mr + gid,     ks + tig + 4);
                ah[mt][3] = ASM(buf, 0, mr + gid + 8, ks + tig + 4);
                al[mt][0] = ASM(buf, 1, mr + gid,     ks + tig);
                al[mt][1] = ASM(buf, 1, mr + gid + 8, ks + tig);
                al[mt][2] = ASM(buf, 1, mr + gid,     ks + tig + 4);
                al[mt][3] = ASM(buf, 1, mr + gid + 8, ks + tig + 4);
            }
            uint32_t bh[4][2], bl[4][2];
#pragma unroll
            for (int nt = 0; nt < 4; nt++) {
                const int nc = wn * 32 + nt * 8 + gid;
                bh[nt][0] = BSM(buf, 0, ks + tig,     nc);
                bh[nt][1] = BSM(buf, 0, ks + tig + 4, nc);
                bl[nt][0] = BSM(buf, 1, ks + tig,     nc);
                bl[nt][1] = BSM(buf, 1, ks + tig + 4, nc);
            }
#pragma unroll
            for (int mt = 0; mt < 4; mt++)
#pragma unroll
                for (int nt = 0; nt < 4; nt++) {
                    mma_tf32(acc[mt][nt], ah[mt], bh[nt]);
                    mma_tf32(acc[mt][nt], al[mt], bh[nt]);
                    mma_tf32(acc[mt][nt], ah[mt], bl[nt]);
                }
        }

        if (c < DIN_ / 16 - 1) {
#pragma unroll
            for (int i = 0; i < 2; i++) {
                const float af[4] = { av[i].x, av[i].y, av[i].z, av[i].w };
                const float bf[4] = { bvv[i].x, bvv[i].y, bvv[i].z, bvv[i].w };
#pragma unroll
                for (int u = 0; u < 4; u++) {
                    uint32_t h = f2tf(af[u]);
                    ASM(buf ^ 1, 0, am + i * 64, akg * 4 + u) = h;
                    ASM(buf ^ 1, 1, am + i * 64, akg * 4 + u) = f2tf(af[u] - __uint_as_float(h));
                    uint32_t hb = f2tf(bf[u]);
                    BSM(buf ^ 1, 0, bk + i * 8, bn4 + u) = hb;
                    BSM(buf ^ 1, 1, bk + i * 8, bn4 + u) = f2tf(bf[u] - __uint_as_float(hb));
                }
            }
            __syncthreads();
        }
    }

    // ---- epilogue: bias + store ----
    float* proj_out = (which == 0) ? g_q : (which == 1) ? g_k : g_v;
#pragma unroll
    for (int mt = 0; mt < 4; mt++) {
#pragma unroll
        for (int nt = 0; nt < 4; nt++) {
            const int cc = wn * 32 + nt * 8 + 2 * tig;
            const int ng = by * 128 + cc;
            const float b0 = bias[ng], b1 = bias[ng + 1];
#pragma unroll
            for (int half = 0; half < 2; half++) {
                const int m = m0 + wm * 64 + mt * 16 + gid + half * 8;
                float2 o;
                o.x = acc[mt][nt][half * 2 + 0] + b0;
                o.y = acc[mt][nt][half * 2 + 1] + b1;
                if (which != 3) {
                    const int nn = m >> 11;
                    const int kk = m & (K_ - 1);
                    const int h  = ng >> 6;
                    const int d  = ng & 63;
                    *(float2*)(proj_out + (((size_t)(nn * H_ + h) * K_ + kk) * D_ + d)) = o;
                } else {
                    *(float2*)(Cflat + (size_t)m * HD_ + ng) = o;
                }
            }
        }
    }
}

// ===========================================================================
// Flash attention on mma.sync tf32.
// grid (16 q-tiles of 128, 32 nh), block 256 (8 warps; warp w owns q-rows
// [16w,16w+16) -> softmax rows never cross warps; P is warp-local).
// QK: 3xTF32 (exact). PV: V split hi/lo, P single rna-tf32.
// smem: Kh/Kl[64][72] (d-major, transposed), Vh/Vl[64][72] (j-major),
//       Ps[128][68] (P, also Q fp32 staging in prologue).
// ===========================================================================
#define FTK 72
#define FTP 68
#define FLASH_SMEM ((4 * 64 * FTK + 128 * FTP) * 4)

__global__ __launch_bounds__(256, 1) void flash_mma()
{
    extern __shared__ uint32_t sm[];
    uint32_t* Kh = sm;
    uint32_t* Kl = Kh + 64 * FTK;
    uint32_t* Vh = Kl + 64 * FTK;
    uint32_t* Vl = Vh + 64 * FTK;
    uint32_t* Ps = Vl + 64 * FTK;

    const int qt = blockIdx.x, nh = blockIdx.y;
    const int n = nh >> 4, h = nh & 15;
    const int tid = threadIdx.x;
    const int w = tid >> 5, lane = tid & 31;
    const int gid = lane >> 2, tig = lane & 3;

    const float* Qg = g_q + ((size_t)nh * K_ + qt * 128) * D_;
    const float* Kg = g_k + (size_t)nh * K_ * D_;
    const float* Vg = g_v + (size_t)nh * K_ * D_;

    // ---- stage Q (fp32) into Ps, then build persistent register fragments ----
#pragma unroll
    for (int i = 0; i < 8; i++) {
        const int idx = tid + i * 256;
        const int row = idx >> 4, c4 = (idx & 15) << 2;
        float4 q = *(const float4*)(Qg + (size_t)row * D_ + c4);
        uint32_t* p = Ps + row * FTP + c4;
        p[0] = __float_as_uint(q.x); p[1] = __float_as_uint(q.y);
        p[2] = __float_as_uint(q.z); p[3] = __float_as_uint(q.w);
    }
    __syncthreads();

    const int r0 = w * 16 + gid;
    uint32_t afh[8][4], afl[8][4];
#pragma unroll
    for (int ks = 0; ks < 8; ks++) {
#pragma unroll
        for (int u = 0; u < 4; u++) {
            const int row = r0 + (u & 1) * 8;
            const int col = ks * 8 + tig + (u >> 1) * 4;
            const float x = __uint_as_float(Ps[row * FTP + col]);
            const uint32_t xh = f2tf(x);
            afh[ks][u] = xh;
            afl[ks][u] = f2tf(x - __uint_as_float(xh));
        }
    }

    float o[8][4] = {};
    float mrow[2] = { -FLT_MAX, -FLT_MAX };
    float lrow[2] = {};

    const uint32_t* mb0 = g_mb + (size_t)(n * K_ + qt * 128 + r0) * (K_ / 32);
    const uint32_t* mb1 = mb0 + 8 * (K_ / 32);

    for (int kt = 0; kt < 32; kt++) {
        __syncthreads();   // prior PV reads of K/V done; first iter: Q staging reads done

        // ---- load K (transpose + split) ----
        {
            const int j = tid & 63;
            const int db = tid >> 6;
#pragma unroll
            for (int i = 0; i < 4; i++) {
                const int d0 = (db + i * 4) << 2;
                float4 kx = *(const float4*)(Kg + (size_t)(kt * 64 + j) * D_ + d0);
                const float kf[4] = { kx.x, kx.y, kx.z, kx.w };
#pragma unroll
                for (int u = 0; u < 4; u++) {
                    const uint32_t hh = f2tf(kf[u]);
                    Kh[(d0 + u) * FTK + j] = hh;
                    Kl[(d0 + u) * FTK + j] = f2tf(kf[u] - __uint_as_float(hh));
                }
            }
        }
        // ---- load V (straight + split), d-major lane mapping ----
        {
            const int d4 = (tid & 15) << 2;
            const int jb = tid >> 4;
#pragma unroll
            for (int i = 0; i < 4; i++) {
                const int j = jb + i * 16;
                float4 vx = *(const float4*)(Vg + (size_t)(kt * 64 + j) * D_ + d4);
                const float vf[4] = { vx.x, vx.y, vx.z, vx.w };
#pragma unroll
                for (int u = 0; u < 4; u++) {
                    const uint32_t hh = f2tf(vf[u]);
                    Vh[j * FTK + d4 + u] = hh;
                    Vl[j * FTK + d4 + u] = f2tf(vf[u] - __uint_as_float(hh));
                }
            }
        }
        __syncthreads();

        // ---- S = Q K^T (3xTF32) ----
        float s[8][4] = {};
#pragma unroll
        for (int ks = 0; ks < 8; ks++) {
#pragma unroll
            for (int nt = 0; nt < 8; nt++) {
                const int rk0 = (ks * 8 + tig) * FTK + nt * 8 + gid;
                uint32_t bh[2] = { Kh[rk0], Kh[rk0 + 4 * FTK] };
                uint32_t bl[2] = { Kl[rk0], Kl[rk0 + 4 * FTK] };
                mma_tf32(s[nt], afh[ks], bh);
                mma_tf32(s[nt], afl[ks], bh);
                mma_tf32(s[nt], afh[ks], bl);
            }
        }

        // ---- mask + scale ----
        const uint2 m0 = *(const uint2*)(mb0 + kt * 2);
        const uint2 m1 = *(const uint2*)(mb1 + kt * 2);
#pragma unroll
        for (int nt = 0; nt < 8; nt++) {
            const int jb = nt * 8 + 2 * tig;
#pragma unroll
            for (int cc = 0; cc < 4; cc++) {
                const int j = jb + (cc & 1);
                const uint32_t word = (cc < 2) ? ((j < 32) ? m0.x : m0.y)
                                               : ((j < 32) ? m1.x : m1.y);
                const bool bit = (word >> (j & 31)) & 1u;
                s[nt][cc] = bit ? -1e9f : s[nt][cc] * 0.125f;
            }
        }

        // ---- online softmax (rows r0, r0+8; quad-local reductions) ----
        float mx0 = -FLT_MAX, mx1 = -FLT_MAX;
#pragma unroll
        for (int nt = 0; nt < 8; nt++) {
            mx0 = fmaxf(mx0, fmaxf(s[nt][0], s[nt][1]));
            mx1 = fmaxf(mx1, fmaxf(s[nt][2], s[nt][3]));
        }
        mx0 = fmaxf(mx0, __shfl_xor_sync(0xffffffffu, mx0, 1));
        mx0 = fmaxf(mx0, __shfl_xor_sync(0xffffffffu, mx0, 2));
        mx1 = fmaxf(mx1, __shfl_xor_sync(0xffffffffu, mx1, 1));
        mx1 = fmaxf(mx1, __shfl_xor_sync(0xffffffffu, mx1, 2));

        const float mn0 = fmaxf(mrow[0], mx0), mn1 = fmaxf(mrow[1], mx1);
        const float f0 = __expf(mrow[0] - mn0), f1 = __expf(mrow[1] - mn1);
        mrow[0] = mn0; mrow[1] = mn1;

        float sum0 = 0.f, sum1 = 0.f;
#pragma unroll
        for (int nt = 0; nt < 8; nt++) {
            s[nt][0] = __expf(s[nt][0] - mn0);
            s[nt][1] = __expf(s[nt][1] - mn0);
            s[nt][2] = __expf(s[nt][2] - mn1);
            s[nt][3] = __expf(s[nt][3] - mn1);
            sum0 += s[nt][0] + s[nt][1];
            sum1 += s[nt][2] + s[nt][3];
        }
        sum0 += __shfl_xor_sync(0xffffffffu, sum0, 1);
        sum0 += __shfl_xor_sync(0xffffffffu, sum0, 2);
        sum1 += __shfl_xor_sync(0xffffffffu, sum1, 1);
        sum1 += __shfl_xor_sync(0xffffffffu, sum1, 2);
        lrow[0] = lrow[0] * f0 + sum0;
        lrow[1] = lrow[1] * f1 + sum1;
#pragma unroll
        for (int dn = 0; dn < 8; dn++) {
            o[dn][0] *= f0; o[dn][1] *= f0;
            o[dn][2] *= f1; o[dn][3] *= f1;
        }

        // ---- write P (rna tf32) — warp-local rows, so only __syncwarp ----
#pragma unroll
        for (int nt = 0; nt < 8; nt++) {
            const int jb = nt * 8 + 2 * tig;
            Ps[r0 * FTP + jb]           = f2tf(s[nt][0]);
            Ps[r0 * FTP + jb + 1]       = f2tf(s[nt][1]);
            Ps[(r0 + 8) * FTP + jb]     = f2tf(s[nt][2]);
            Ps[(r0 + 8) * FTP + jb + 1] = f2tf(s[nt][3]);
        }
        __syncwarp();

        // ---- O += P V (2 passes: Vh + Vl) ----
#pragma unroll
        for (int ks = 0; ks < 8; ks++) {
            uint32_t ap[4];
            ap[0] = Ps[r0 * FTP + ks * 8 + tig];
            ap[1] = Ps[(r0 + 8) * FTP + ks * 8 + tig];
            ap[2] = Ps[r0 * FTP + ks * 8 + tig + 4];
            ap[3] = Ps[(r0 + 8) * FTP + ks * 8 + tig + 4];
#pragma unroll
            for (int dn = 0; dn < 8; dn++) {
                const int v0 = (ks * 8 + tig) * FTK + dn * 8 + gid;
                uint32_t bh[2] = { Vh[v0], Vh[v0 + 4 * FTK] };
                uint32_t bl[2] = { Vl[v0], Vl[v0 + 4 * FTK] };
                mma_tf32(o[dn], ap, bh);
                mma_tf32(o[dn], ap, bl);
            }
        }
    }

    // ---- epilogue ----
    const float i0 = 1.0f / lrow[0], i1 = 1.0f / lrow[1];
    const size_t row0 = (size_t)n * K_ + qt * 128 + r0;
#pragma unroll
    for (int dn = 0; dn < 8; dn++) {
        const int col = h * 64 + dn * 8 + 2 * tig;
        *(float2*)(g_y + row0 * HD_ + col) =
            make_float2(o[dn][0] * i0, o[dn][1] * i0);
        *(float2*)(g_y + (row0 + 8) * HD_ + col) =
            make_float2(o[dn][2] * i1, o[dn][3] * i1);
    }
}

// ===========================================================================
extern "C" void kernel_launch(void* const* d_in, const int* in_sizes, int n_in,
                              void* d_out, int out_size)
{
    const float* query = (const float*)d_in[0];
    const float* key   = (const float*)d_in[1];
    const float* value = (const float*)d_in[2];
    const int*   mask  = (const int*)d_in[3];
    const float* Wq = (const float*)d_in[4];
    const float* bq = (const float*)d_in[5];
    const float* Wk = (const float*)d_in[6];
    const float* bk = (const float*)d_in[7];
    const float* Wv = (const float*)d_in[8];
    const float* bv = (const float*)d_in[9];
    const float* Wp = (const float*)d_in[10];
    const float* bp = (const float*)d_in[11];
    float* out = (float*)d_out;

    cudaFuncSetAttribute(gemm_mma, cudaFuncAttributeMaxDynamicSharedMemorySize, GEMM_SMEM);
    cudaFuncSetAttribute(flash_mma, cudaFuncAttributeMaxDynamicSharedMemorySize, FLASH_SMEM);

    mask_pack<<<(N_ * K_ * K_) / 256, 256>>>(mask);

    dim3 gg(32, 8), gb(256);
    gemm_mma<<<gg, gb, GEMM_SMEM>>>(query, Wq, bq, nullptr, 64, 63, 65536, 0);
    gemm_mma<<<gg, gb, GEMM_SMEM>>>(key,   Wk, bk, nullptr, 64, 63, 65536, 1);
    gemm_mma<<<gg, gb, GEMM_SMEM>>>(value, Wv, bv, nullptr, 64, 63, 65536, 2);

    dim3 gf(16, 32);
    flash_mma<<<gf, gb, FLASH_SMEM>>>();

    gemm_mma<<<gg, gb, GEMM_SMEM>>>(nullptr, Wp, bp, out, 1024, 1023, 0, 3);
}

// round 6
// speedup vs baseline: 2.6717x; 1.7568x over previous
#include <cuda_runtime.h>
#include <cstdint>
#include <float.h>

// Problem constants
#define N_   2
#define K_   2048
#define DIN_ 1024
#define H_   16
#define D_   64          // DOUT
#define HD_  1024        // H_*D_

// Scratch (device globals: allocation-free)
__device__ float g_q[(size_t)N_ * H_ * K_ * D_];   // (n,h,k,d)
__device__ float g_k[(size_t)N_ * H_ * K_ * D_];
__device__ float g_v[(size_t)N_ * H_ * K_ * D_];
__device__ float g_y[(size_t)N_ * K_ * HD_];       // (n,k,h*64+d)
__device__ uint32_t g_mb[(size_t)N_ * K_ * (K_ / 32)];  // packed mask bits

// Split x0,x1 (even,odd k) into packed bf16x2 hi (truncation) + lo (residual, rn).
// hi: low16 = hi16(x0), high16 = hi16(x1). Residual lo captures the rest exactly
// to within bf16-rn of the residual (~2^-16 relative overall for 3-term product).
__device__ __forceinline__ void bsplit(float x0, float x1, uint32_t& h, uint32_t& l) {
    const uint32_t u0 = __float_as_uint(x0), u1 = __float_as_uint(x1);
    h = __byte_perm(u0, u1, 0x7632);
    const float r0 = x0 - __uint_as_float(u0 & 0xffff0000u);
    const float r1 = x1 - __uint_as_float(u1 & 0xffff0000u);
    asm("cvt.rn.bf16x2.f32 %0, %1, %2;" : "=r"(l) : "f"(r1), "f"(r0));
}

__device__ __forceinline__ void mma_bf16(float* c, const uint32_t* a, const uint32_t* b) {
    asm volatile(
        "mma.sync.aligned.m16n8k16.row.col.f32.bf16.bf16.f32 "
        "{%0,%1,%2,%3}, {%4,%5,%6,%7}, {%8,%9}, {%0,%1,%2,%3};"
        : "+f"(c[0]), "+f"(c[1]), "+f"(c[2]), "+f"(c[3])
        : "r"(a[0]), "r"(a[1]), "r"(a[2]), "r"(a[3]), "r"(b[0]), "r"(b[1]));
}

// ===========================================================================
// Mask pack: g_mb bit j of word (n*K + i)*64 + j/32  = mask[n,i,j] != 0
// ===========================================================================
__global__ __launch_bounds__(256) void mask_pack(const int* __restrict__ mask)
{
    const int idx = blockIdx.x * 256 + threadIdx.x;
    const int v = mask[idx];
    const uint32_t b = __ballot_sync(0xffffffffu, v != 0);
    if ((threadIdx.x & 31) == 0) g_mb[idx >> 5] = b;
}

// ===========================================================================
// 3x split-bf16 mma GEMM: C(4096 x 1024) = A(4096x1024) @ B + bias
// grid (32 M-tiles, 8 N-tiles), block 256 (8 warps: 2m x 4n, warp tile 64x32)
// acc = Ah*Bh + Al*Bh + Ah*Bl   (~fp32-accurate: dropped ll term ~2^-16)
//   proj:    ldb=64,   n_mask=63,   hs=65536  (W is (H,1024,64))
//   outproj: ldb=1024, n_mask=1023, hs=0
// which: 0->g_q 1->g_k 2->g_v (proj (n,h,k,d) layout), 3->Cflat row-major
// smem words: A = 2buf*2hl*128rows*12(kp 0..7 +pad) = 6144
//             B = 2buf*2hl*8kp*136(n +pad)          = 4352   -> 41984 B
// ===========================================================================
#define AP(b,hl,r,c) gsm[(((b)*2+(hl))*128 + (r))*12 + (c)]
#define BP(b,hl,r,c) gsm[6144 + (((b)*2+(hl))*8 + (r))*136 + (c)]
#define GEMM_SMEM ((6144 + 4352) * 4)

__global__ __launch_bounds__(256) void gemm_mma(
    const float* __restrict__ Ain, const float* __restrict__ B,
    const float* __restrict__ bias, float* __restrict__ Cflat,
    int ldb, int n_mask, int hs, int which)
{
    extern __shared__ uint32_t gsm[];

    const int tid  = threadIdx.x;
    const int wid  = tid >> 5;
    const int lane = tid & 31;
    const int gid  = lane >> 2;
    const int tig  = lane & 3;
    const int wm   = wid >> 2;
    const int wn   = wid & 3;

    const int m0 = blockIdx.x * 128;
    const int by = blockIdx.y;

    const float* A = (which == 3) ? g_y : Ain;

    // loader mappings
    const int am  = tid >> 2;          // A row (and +64)
    const int akg = tid & 3;           // A k-group of 4 -> kpairs akg*2, akg*2+1
    const int bkp = tid >> 5;          // B kpair 0..7
    const int bn4 = (tid & 31) << 2;   // B n group of 4

    const int ngb = by * 128 + bn4;
    const size_t bcol = (size_t)(ngb & n_mask) + (size_t)(ngb >> 6) * hs;

    float acc[4][4][4] = {};
    float4 av[2], b0v, b1v;

    // ---- prologue: load + split chunk 0 ----
#pragma unroll
    for (int i = 0; i < 2; i++)
        av[i] = *(const float4*)(A + (size_t)(m0 + am + i * 64) * DIN_ + akg * 4);
    b0v = *(const float4*)(B + (size_t)(2 * bkp) * ldb + bcol);
    b1v = *(const float4*)(B + (size_t)(2 * bkp + 1) * ldb + bcol);

#pragma unroll
    for (int i = 0; i < 2; i++) {
        uint32_t h0, l0, h1, l1;
        bsplit(av[i].x, av[i].y, h0, l0);
        bsplit(av[i].z, av[i].w, h1, l1);
        *(uint2*)&AP(0, 0, am + i * 64, akg * 2) = make_uint2(h0, h1);
        *(uint2*)&AP(0, 1, am + i * 64, akg * 2) = make_uint2(l0, l1);
    }
    {
        const float a0[4] = { b0v.x, b0v.y, b0v.z, b0v.w };
        const float a1[4] = { b1v.x, b1v.y, b1v.z, b1v.w };
        uint32_t h[4], l[4];
#pragma unroll
        for (int u = 0; u < 4; u++) bsplit(a0[u], a1[u], h[u], l[u]);
        *(uint4*)&BP(0, 0, bkp, bn4) = make_uint4(h[0], h[1], h[2], h[3]);
        *(uint4*)&BP(0, 1, bkp, bn4) = make_uint4(l[0], l[1], l[2], l[3]);
    }
    __syncthreads();

    for (int c = 0; c < DIN_ / 16; c++) {
        const int buf = c & 1;

        if (c < DIN_ / 16 - 1) {
            const int kc = (c + 1) * 16;
#pragma unroll
            for (int i = 0; i < 2; i++)
                av[i] = *(const float4*)(A + (size_t)(m0 + am + i * 64) * DIN_ + kc + akg * 4);
            b0v = *(const float4*)(B + (size_t)(kc + 2 * bkp) * ldb + bcol);
            b1v = *(const float4*)(B + (size_t)(kc + 2 * bkp + 1) * ldb + bcol);
        }

        // ---- one k16 mma step ----
        uint32_t ah[4][4], al[4][4];
#pragma unroll
        for (int mt = 0; mt < 4; mt++) {
            const int mr = wm * 64 + mt * 16;
            ah[mt][0] = AP(buf, 0, mr + gid,     tig);
            ah[mt][1] = AP(buf, 0, mr + gid + 8, tig);
            ah[mt][2] = AP(buf, 0, mr + gid,     tig + 4);
            ah[mt][3] = AP(buf, 0, mr + gid + 8, tig + 4);
            al[mt][0] = AP(buf, 1, mr + gid,     tig);
            al[mt][1] = AP(buf, 1, mr + gid + 8, tig);
            al[mt][2] = AP(buf, 1, mr + gid,     tig + 4);
            al[mt][3] = AP(buf, 1, mr + gid + 8, tig + 4);
        }
        uint32_t bh[4][2], bl[4][2];
#pragma unroll
        for (int nt = 0; nt < 4; nt++) {
            const int nc = wn * 32 + nt * 8 + gid;
            bh[nt][0] = BP(buf, 0, tig,     nc);
            bh[nt][1] = BP(buf, 0, tig + 4, nc);
            bl[nt][0] = BP(buf, 1, tig,     nc);
            bl[nt][1] = BP(buf, 1, tig + 4, nc);
        }
#pragma unroll
        for (int mt = 0; mt < 4; mt++)
#pragma unroll
            for (int nt = 0; nt < 4; nt++) {
                mma_bf16(acc[mt][nt], ah[mt], bh[nt]);
                mma_bf16(acc[mt][nt], al[mt], bh[nt]);
                mma_bf16(acc[mt][nt], ah[mt], bl[nt]);
            }

        if (c < DIN_ / 16 - 1) {
#pragma unroll
            for (int i = 0; i < 2; i++) {
                uint32_t h0, l0, h1, l1;
                bsplit(av[i].x, av[i].y, h0, l0);
                bsplit(av[i].z, av[i].w, h1, l1);
                *(uint2*)&AP(buf ^ 1, 0, am + i * 64, akg * 2) = make_uint2(h0, h1);
                *(uint2*)&AP(buf ^ 1, 1, am + i * 64, akg * 2) = make_uint2(l0, l1);
            }
            const float a0[4] = { b0v.x, b0v.y, b0v.z, b0v.w };
            const float a1[4] = { b1v.x, b1v.y, b1v.z, b1v.w };
            uint32_t h[4], l[4];
#pragma unroll
            for (int u = 0; u < 4; u++) bsplit(a0[u], a1[u], h[u], l[u]);
            *(uint4*)&BP(buf ^ 1, 0, bkp, bn4) = make_uint4(h[0], h[1], h[2], h[3]);
            *(uint4*)&BP(buf ^ 1, 1, bkp, bn4) = make_uint4(l[0], l[1], l[2], l[3]);
            __syncthreads();
        }
    }

    // ---- epilogue: bias + store ----
    float* proj_out = (which == 0) ? g_q : (which == 1) ? g_k : g_v;
#pragma unroll
    for (int mt = 0; mt < 4; mt++) {
#pragma unroll
        for (int nt = 0; nt < 4; nt++) {
            const int cc = wn * 32 + nt * 8 + 2 * tig;
            const int ng = by * 128 + cc;
            const float b0 = bias[ng], b1 = bias[ng + 1];
#pragma unroll
            for (int half = 0; half < 2; half++) {
                const int m = m0 + wm * 64 + mt * 16 + gid + half * 8;
                float2 o;
                o.x = acc[mt][nt][half * 2 + 0] + b0;
                o.y = acc[mt][nt][half * 2 + 1] + b1;
                if (which != 3) {
                    const int nn = m >> 11;
                    const int kk = m & (K_ - 1);
                    const int h  = ng >> 6;
                    const int d  = ng & 63;
                    *(float2*)(proj_out + (((size_t)(nn * H_ + h) * K_ + kk) * D_ + d)) = o;
                } else {
                    *(float2*)(Cflat + (size_t)m * HD_ + ng) = o;
                }
            }
        }
    }
}

// ===========================================================================
// Flash attention on split-bf16 mma.
// grid (16 q-tiles of 128, 32 nh), block 256 (8 warps; warp w owns q-rows
// [16w,16w+16) -> softmax rows and P warp-local).
// QK: qh*kh + ql*kh + qh*kl.  PV: ph*vh + ph*vl + pl*vh.
// smem words: Kh/Kl[32 dp][72], Vh/Vl[32 jp][72], Ph/Pl[128][36]  = 18432
// ===========================================================================
#define KST 72
#define PST 36
#define QST 68
#define FLASH_SMEM (18432 * 4)

__global__ __launch_bounds__(256, 2) void flash_mma()
{
    extern __shared__ uint32_t sm[];
    uint32_t* Kh = sm;
    uint32_t* Kl = sm + 2304;
    uint32_t* Vh = sm + 4608;
    uint32_t* Vl = sm + 6912;
    uint32_t* Ph = sm + 9216;
    uint32_t* Pl = sm + 13824;
    uint32_t* Qst = sm + 9216;   // fp32 Q staging (consumed before P writes)

    const int qt = blockIdx.x, nh = blockIdx.y;
    const int n = nh >> 4, h = nh & 15;
    const int tid = threadIdx.x;
    const int w = tid >> 5, lane = tid & 31;
    const int gid = lane >> 2, tig = lane & 3;

    const float* Qg = g_q + ((size_t)nh * K_ + qt * 128) * D_;
    const float* Kg = g_k + (size_t)nh * K_ * D_;
    const float* Vg = g_v + (size_t)nh * K_ * D_;

    // ---- stage Q (fp32), then build persistent packed fragments ----
#pragma unroll
    for (int i = 0; i < 8; i++) {
        const int idx = tid + i * 256;
        const int row = idx >> 4, c4 = (idx & 15) << 2;
        float4 q = *(const float4*)(Qg + (size_t)row * D_ + c4);
        uint32_t* p = Qst + row * QST + c4;
        p[0] = __float_as_uint(q.x); p[1] = __float_as_uint(q.y);
        p[2] = __float_as_uint(q.z); p[3] = __float_as_uint(q.w);
    }
    __syncthreads();

    const int r0 = w * 16 + gid;
    uint32_t afh[4][4], afl[4][4];
#pragma unroll
    for (int sp = 0; sp < 4; sp++) {
        const int de = 16 * sp + 2 * tig;
#pragma unroll
        for (int u = 0; u < 4; u++) {
            const int row = r0 + (u & 1) * 8;
            const int col = de + (u >> 1) * 8;
            const float x0 = __uint_as_float(Qst[row * QST + col]);
            const float x1 = __uint_as_float(Qst[row * QST + col + 1]);
            bsplit(x0, x1, afh[sp][u], afl[sp][u]);
        }
    }

    float o[8][4] = {};
    float mrow[2] = { -FLT_MAX, -FLT_MAX };
    float lrow[2] = {};

    const uint32_t* mb0 = g_mb + (size_t)(n * K_ + qt * 128 + r0) * (K_ / 32);
    const uint32_t* mb1 = mb0 + 8 * (K_ / 32);

    for (int kt = 0; kt < 32; kt++) {
        __syncthreads();   // prior PV reads done; first iter: Q staging reads done

        // ---- load K (transpose + split, packed over d pairs) ----
        {
            const int j = tid & 63;
            const int db = tid >> 6;
#pragma unroll
            for (int i = 0; i < 4; i++) {
                const int d0 = (db + i * 4) << 2;
                float4 kx = *(const float4*)(Kg + (size_t)(kt * 64 + j) * D_ + d0);
                uint32_t h0, l0, h1, l1;
                bsplit(kx.x, kx.y, h0, l0);
                bsplit(kx.z, kx.w, h1, l1);
                const int dp = d0 >> 1;
                Kh[dp * KST + j] = h0; Kh[(dp + 1) * KST + j] = h1;
                Kl[dp * KST + j] = l0; Kl[(dp + 1) * KST + j] = l1;
            }
        }
        // ---- load V (split, packed over j pairs) ----
        {
            const int d4 = (tid & 15) << 2;
            const int jb = tid >> 4;
#pragma unroll
            for (int i = 0; i < 2; i++) {
                const int jp = jb + i * 16;
                const float* va = Vg + (size_t)(kt * 64 + 2 * jp) * D_ + d4;
                float4 v0 = *(const float4*)va;
                float4 v1 = *(const float4*)(va + D_);
                const float e0[4] = { v0.x, v0.y, v0.z, v0.w };
                const float e1[4] = { v1.x, v1.y, v1.z, v1.w };
                uint32_t hh[4], ll[4];
#pragma unroll
                for (int u = 0; u < 4; u++) bsplit(e0[u], e1[u], hh[u], ll[u]);
                *(uint4*)&Vh[jp * KST + d4] = make_uint4(hh[0], hh[1], hh[2], hh[3]);
                *(uint4*)&Vl[jp * KST + d4] = make_uint4(ll[0], ll[1], ll[2], ll[3]);
            }
        }
        __syncthreads();

        // ---- S = Q K^T ----
        float s[8][4] = {};
#pragma unroll
        for (int sp = 0; sp < 4; sp++) {
#pragma unroll
            for (int nt = 0; nt < 8; nt++) {
                const int i0 = (sp * 8 + tig) * KST + nt * 8 + gid;
                uint32_t bh[2] = { Kh[i0], Kh[i0 + 4 * KST] };
                uint32_t bl[2] = { Kl[i0], Kl[i0 + 4 * KST] };
                mma_bf16(s[nt], afh[sp], bh);
                mma_bf16(s[nt], afl[sp], bh);
                mma_bf16(s[nt], afh[sp], bl);
            }
        }

        // ---- mask + scale ----
        const uint2 m0 = *(const uint2*)(mb0 + kt * 2);
        const uint2 m1 = *(const uint2*)(mb1 + kt * 2);
#pragma unroll
        for (int nt = 0; nt < 8; nt++) {
            const int jb = nt * 8 + 2 * tig;
#pragma unroll
            for (int cc = 0; cc < 4; cc++) {
                const int j = jb + (cc & 1);
                const uint32_t word = (cc < 2) ? ((j < 32) ? m0.x : m0.y)
                                               : ((j < 32) ? m1.x : m1.y);
                const bool bit = (word >> (j & 31)) & 1u;
                s[nt][cc] = bit ? -1e9f : s[nt][cc] * 0.125f;
            }
        }

        // ---- online softmax (rows r0, r0+8) ----
        float mx0 = -FLT_MAX, mx1 = -FLT_MAX;
#pragma unroll
        for (int nt = 0; nt < 8; nt++) {
            mx0 = fmaxf(mx0, fmaxf(s[nt][0], s[nt][1]));
            mx1 = fmaxf(mx1, fmaxf(s[nt][2], s[nt][3]));
        }
        mx0 = fmaxf(mx0, __shfl_xor_sync(0xffffffffu, mx0, 1));
        mx0 = fmaxf(mx0, __shfl_xor_sync(0xffffffffu, mx0, 2));
        mx1 = fmaxf(mx1, __shfl_xor_sync(0xffffffffu, mx1, 1));
        mx1 = fmaxf(mx1, __shfl_xor_sync(0xffffffffu, mx1, 2));

        const float mn0 = fmaxf(mrow[0], mx0), mn1 = fmaxf(mrow[1], mx1);
        const float f0 = __expf(mrow[0] - mn0), f1 = __expf(mrow[1] - mn1);
        mrow[0] = mn0; mrow[1] = mn1;

        float sum0 = 0.f, sum1 = 0.f;
#pragma unroll
        for (int nt = 0; nt < 8; nt++) {
            s[nt][0] = __expf(s[nt][0] - mn0);
            s[nt][1] = __expf(s[nt][1] - mn0);
            s[nt][2] = __expf(s[nt][2] - mn1);
            s[nt][3] = __expf(s[nt][3] - mn1);
            sum0 += s[nt][0] + s[nt][1];
            sum1 += s[nt][2] + s[nt][3];
        }
        sum0 += __shfl_xor_sync(0xffffffffu, sum0, 1);
        sum0 += __shfl_xor_sync(0xffffffffu, sum0, 2);
        sum1 += __shfl_xor_sync(0xffffffffu, sum1, 1);
        sum1 += __shfl_xor_sync(0xffffffffu, sum1, 2);
        lrow[0] = lrow[0] * f0 + sum0;
        lrow[1] = lrow[1] * f1 + sum1;
#pragma unroll
        for (int dn = 0; dn < 8; dn++) {
            o[dn][0] *= f0; o[dn][1] *= f0;
            o[dn][2] *= f1; o[dn][3] *= f1;
        }

        // ---- write P split (warp-local rows) ----
#pragma unroll
        for (int nt = 0; nt < 8; nt++) {
            uint32_t hh, ll;
            bsplit(s[nt][0], s[nt][1], hh, ll);
            Ph[r0 * PST + nt * 4 + tig] = hh;
            Pl[r0 * PST + nt * 4 + tig] = ll;
            bsplit(s[nt][2], s[nt][3], hh, ll);
            Ph[(r0 + 8) * PST + nt * 4 + tig] = hh;
            Pl[(r0 + 8) * PST + nt * 4 + tig] = ll;
        }
        __syncwarp();

        // ---- O += P V ----
#pragma unroll
        for (int sp = 0; sp < 4; sp++) {
            uint32_t aph[4], apl[4];
            aph[0] = Ph[r0 * PST + sp * 8 + tig];
            aph[1] = Ph[(r0 + 8) * PST + sp * 8 + tig];
            aph[2] = Ph[r0 * PST + sp * 8 + tig + 4];
            aph[3] = Ph[(r0 + 8) * PST + sp * 8 + tig + 4];
            apl[0] = Pl[r0 * PST + sp * 8 + tig];
            apl[1] = Pl[(r0 + 8) * PST + sp * 8 + tig];
            apl[2] = Pl[r0 * PST + sp * 8 + tig + 4];
            apl[3] = Pl[(r0 + 8) * PST + sp * 8 + tig + 4];
#pragma unroll
            for (int dn = 0; dn < 8; dn++) {
                const int v0 = (sp * 8 + tig) * KST + dn * 8 + gid;
                uint32_t bh[2] = { Vh[v0], Vh[v0 + 4 * KST] };
                uint32_t bl[2] = { Vl[v0], Vl[v0 + 4 * KST] };
                mma_bf16(o[dn], aph, bh);
                mma_bf16(o[dn], aph, bl);
                mma_bf16(o[dn], apl, bh);
            }
        }
    }

    // ---- epilogue ----
    const float i0 = 1.0f / lrow[0], i1 = 1.0f / lrow[1];
    const size_t row0 = (size_t)n * K_ + qt * 128 + r0;
#pragma unroll
    for (int dn = 0; dn < 8; dn++) {
        const int col = h * 64 + dn * 8 + 2 * tig;
        *(float2*)(g_y + row0 * HD_ + col) =
            make_float2(o[dn][0] * i0, o[dn][1] * i0);
        *(float2*)(g_y + (row0 + 8) * HD_ + col) =
            make_float2(o[dn][2] * i1, o[dn][3] * i1);
    }
}

// ===========================================================================
extern "C" void kernel_launch(void* const* d_in, const int* in_sizes, int n_in,
                              void* d_out, int out_size)
{
    const float* query = (const float*)d_in[0];
    const float* key   = (const float*)d_in[1];
    const float* value = (const float*)d_in[2];
    const int*   mask  = (const int*)d_in[3];
    const float* Wq = (const float*)d_in[4];
    const float* bq = (const float*)d_in[5];
    const float* Wk = (const float*)d_in[6];
    const float* bk = (const float*)d_in[7];
    const float* Wv = (const float*)d_in[8];
    const float* bv = (const float*)d_in[9];
    const float* Wp = (const float*)d_in[10];
    const float* bp = (const float*)d_in[11];
    float* out = (float*)d_out;

    cudaFuncSetAttribute(gemm_mma, cudaFuncAttributeMaxDynamicSharedMemorySize, GEMM_SMEM);
    cudaFuncSetAttribute(flash_mma, cudaFuncAttributeMaxDynamicSharedMemorySize, FLASH_SMEM);

    mask_pack<<<(N_ * K_ * K_) / 256, 256>>>(mask);

    dim3 gg(32, 8), gb(256);
    gemm_mma<<<gg, gb, GEMM_SMEM>>>(query, Wq, bq, nullptr, 64, 63, 65536, 0);
    gemm_mma<<<gg, gb, GEMM_SMEM>>>(key,   Wk, bk, nullptr, 64, 63, 65536, 1);
    gemm_mma<<<gg, gb, GEMM_SMEM>>>(value, Wv, bv, nullptr, 64, 63, 65536, 2);

    dim3 gf(16, 32);
    flash_mma<<<gf, gb, FLASH_SMEM>>>();

    gemm_mma<<<gg, gb, GEMM_SMEM>>>(nullptr, Wp, bp, out, 1024, 1023, 0, 3);
}

// round 7
// speedup vs baseline: 2.6718x; 1.0000x over previous
#include <cuda_runtime.h>
#include <cstdint>
#include <float.h>

// Problem constants
#define N_   2
#define K_   2048
#define DIN_ 1024
#define H_   16
#define D_   64          // DOUT
#define HD_  1024        // H_*D_

// Scratch (device globals: allocation-free)
__device__ float g_q[(size_t)N_ * H_ * K_ * D_];   // (n,h,k,d)
__device__ float g_k[(size_t)N_ * H_ * K_ * D_];
__device__ float g_v[(size_t)N_ * H_ * K_ * D_];
__device__ float g_y[(size_t)N_ * K_ * HD_];       // (n,k,h*64+d)
__device__ uint32_t g_mb[(size_t)N_ * K_ * (K_ / 32)];  // packed mask bits

// Split x0,x1 (even,odd k) into packed bf16x2 hi (truncation) + lo (residual, rn).
// hi: low16 = hi16(x0), high16 = hi16(x1). Residual lo captures the rest exactly
// to within bf16-rn of the residual (~2^-16 relative overall for 3-term product).
__device__ __forceinline__ void bsplit(float x0, float x1, uint32_t& h, uint32_t& l) {
    const uint32_t u0 = __float_as_uint(x0), u1 = __float_as_uint(x1);
    h = __byte_perm(u0, u1, 0x7632);
    const float r0 = x0 - __uint_as_float(u0 & 0xffff0000u);
    const float r1 = x1 - __uint_as_float(u1 & 0xffff0000u);
    asm("cvt.rn.bf16x2.f32 %0, %1, %2;" : "=r"(l) : "f"(r1), "f"(r0));
}

__device__ __forceinline__ void mma_bf16(float* c, const uint32_t* a, const uint32_t* b) {
    asm volatile(
        "mma.sync.aligned.m16n8k16.row.col.f32.bf16.bf16.f32 "
        "{%0,%1,%2,%3}, {%4,%5,%6,%7}, {%8,%9}, {%0,%1,%2,%3};"
        : "+f"(c[0]), "+f"(c[1]), "+f"(c[2]), "+f"(c[3])
        : "r"(a[0]), "r"(a[1]), "r"(a[2]), "r"(a[3]), "r"(b[0]), "r"(b[1]));
}

// ===========================================================================
// Mask pack: g_mb bit j of word (n*K + i)*64 + j/32  = mask[n,i,j] != 0
// ===========================================================================
__global__ __launch_bounds__(256) void mask_pack(const int* __restrict__ mask)
{
    const int idx = blockIdx.x * 256 + threadIdx.x;
    const int v = mask[idx];
    const uint32_t b = __ballot_sync(0xffffffffu, v != 0);
    if ((threadIdx.x & 31) == 0) g_mb[idx >> 5] = b;
}

// ===========================================================================
// 3x split-bf16 mma GEMM: C(4096 x 1024) = A(4096x1024) @ B + bias
// grid (32 M-tiles, 8 N-tiles), block 256 (8 warps: 2m x 4n, warp tile 64x32)
// acc = Ah*Bh + Al*Bh + Ah*Bl   (~fp32-accurate: dropped ll term ~2^-16)
//   proj:    ldb=64,   n_mask=63,   hs=65536  (W is (H,1024,64))
//   outproj: ldb=1024, n_mask=1023, hs=0
// which: 0->g_q 1->g_k 2->g_v (proj (n,h,k,d) layout), 3->Cflat row-major
// smem words: A = 2buf*2hl*128rows*12(kp 0..7 +pad) = 6144
//             B = 2buf*2hl*8kp*136(n +pad)          = 4352   -> 41984 B
// ===========================================================================
#define AP(b,hl,r,c) gsm[(((b)*2+(hl))*128 + (r))*12 + (c)]
#define BP(b,hl,r,c) gsm[6144 + (((b)*2+(hl))*8 + (r))*136 + (c)]
#define GEMM_SMEM ((6144 + 4352) * 4)

__global__ __launch_bounds__(256) void gemm_mma(
    const float* __restrict__ Ain, const float* __restrict__ B,
    const float* __restrict__ bias, float* __restrict__ Cflat,
    int ldb, int n_mask, int hs, int which)
{
    extern __shared__ uint32_t gsm[];

    const int tid  = threadIdx.x;
    const int wid  = tid >> 5;
    const int lane = tid & 31;
    const int gid  = lane >> 2;
    const int tig  = lane & 3;
    const int wm   = wid >> 2;
    const int wn   = wid & 3;

    const int m0 = blockIdx.x * 128;
    const int by = blockIdx.y;

    const float* A = (which == 3) ? g_y : Ain;

    // loader mappings
    const int am  = tid >> 2;          // A row (and +64)
    const int akg = tid & 3;           // A k-group of 4 -> kpairs akg*2, akg*2+1
    const int bkp = tid >> 5;          // B kpair 0..7
    const int bn4 = (tid & 31) << 2;   // B n group of 4

    const int ngb = by * 128 + bn4;
    const size_t bcol = (size_t)(ngb & n_mask) + (size_t)(ngb >> 6) * hs;

    float acc[4][4][4] = {};
    float4 av[2], b0v, b1v;

    // ---- prologue: load + split chunk 0 ----
#pragma unroll
    for (int i = 0; i < 2; i++)
        av[i] = *(const float4*)(A + (size_t)(m0 + am + i * 64) * DIN_ + akg * 4);
    b0v = *(const float4*)(B + (size_t)(2 * bkp) * ldb + bcol);
    b1v = *(const float4*)(B + (size_t)(2 * bkp + 1) * ldb + bcol);

#pragma unroll
    for (int i = 0; i < 2; i++) {
        uint32_t h0, l0, h1, l1;
        bsplit(av[i].x, av[i].y, h0, l0);
        bsplit(av[i].z, av[i].w, h1, l1);
        *(uint2*)&AP(0, 0, am + i * 64, akg * 2) = make_uint2(h0, h1);
        *(uint2*)&AP(0, 1, am + i * 64, akg * 2) = make_uint2(l0, l1);
    }
    {
        const float a0[4] = { b0v.x, b0v.y, b0v.z, b0v.w };
        const float a1[4] = { b1v.x, b1v.y, b1v.z, b1v.w };
        uint32_t h[4], l[4];
#pragma unroll
        for (int u = 0; u < 4; u++) bsplit(a0[u], a1[u], h[u], l[u]);
        *(uint4*)&BP(0, 0, bkp, bn4) = make_uint4(h[0], h[1], h[2], h[3]);
        *(uint4*)&BP(0, 1, bkp, bn4) = make_uint4(l[0], l[1], l[2], l[3]);
    }
    __syncthreads();

    for (int c = 0; c < DIN_ / 16; c++) {
        const int buf = c & 1;

        if (c < DIN_ / 16 - 1) {
            const int kc = (c + 1) * 16;
#pragma unroll
            for (int i = 0; i < 2; i++)
                av[i] = *(const float4*)(A + (size_t)(m0 + am + i * 64) * DIN_ + kc + akg * 4);
            b0v = *(const float4*)(B + (size_t)(kc + 2 * bkp) * ldb + bcol);
            b1v = *(const float4*)(B + (size_t)(kc + 2 * bkp + 1) * ldb + bcol);
        }

        // ---- one k16 mma step ----
        uint32_t ah[4][4], al[4][4];
#pragma unroll
        for (int mt = 0; mt < 4; mt++) {
            const int mr = wm * 64 + mt * 16;
            ah[mt][0] = AP(buf, 0, mr + gid,     tig);
            ah[mt][1] = AP(buf, 0, mr + gid + 8, tig);
            ah[mt][2] = AP(buf, 0, mr + gid,     tig + 4);
            ah[mt][3] = AP(buf, 0, mr + gid + 8, tig + 4);
            al[mt][0] = AP(buf, 1, mr + gid,     tig);
            al[mt][1] = AP(buf, 1, mr + gid + 8, tig);
            al[mt][2] = AP(buf, 1, mr + gid,     tig + 4);
            al[mt][3] = AP(buf, 1, mr + gid + 8, tig + 4);
        }
        uint32_t bh[4][2], bl[4][2];
#pragma unroll
        for (int nt = 0; nt < 4; nt++) {
            const int nc = wn * 32 + nt * 8 + gid;
            bh[nt][0] = BP(buf, 0, tig,     nc);
            bh[nt][1] = BP(buf, 0, tig + 4, nc);
            bl[nt][0] = BP(buf, 1, tig,     nc);
            bl[nt][1] = BP(buf, 1, tig + 4, nc);
        }
#pragma unroll
        for (int mt = 0; mt < 4; mt++)
#pragma unroll
            for (int nt = 0; nt < 4; nt++) {
                mma_bf16(acc[mt][nt], ah[mt], bh[nt]);
                mma_bf16(acc[mt][nt], al[mt], bh[nt]);
                mma_bf16(acc[mt][nt], ah[mt], bl[nt]);
            }

        if (c < DIN_ / 16 - 1) {
#pragma unroll
            for (int i = 0; i < 2; i++) {
                uint32_t h0, l0, h1, l1;
                bsplit(av[i].x, av[i].y, h0, l0);
                bsplit(av[i].z, av[i].w, h1, l1);
                *(uint2*)&AP(buf ^ 1, 0, am + i * 64, akg * 2) = make_uint2(h0, h1);
                *(uint2*)&AP(buf ^ 1, 1, am + i * 64, akg * 2) = make_uint2(l0, l1);
            }
            const float a0[4] = { b0v.x, b0v.y, b0v.z, b0v.w };
            const float a1[4] = { b1v.x, b1v.y, b1v.z, b1v.w };
            uint32_t h[4], l[4];
#pragma unroll
            for (int u = 0; u < 4; u++) bsplit(a0[u], a1[u], h[u], l[u]);
            *(uint4*)&BP(buf ^ 1, 0, bkp, bn4) = make_uint4(h[0], h[1], h[2], h[3]);
            *(uint4*)&BP(buf ^ 1, 1, bkp, bn4) = make_uint4(l[0], l[1], l[2], l[3]);
            __syncthreads();
        }
    }

    // ---- epilogue: bias + store ----
    float* proj_out = (which == 0) ? g_q : (which == 1) ? g_k : g_v;
#pragma unroll
    for (int mt = 0; mt < 4; mt++) {
#pragma unroll
        for (int nt = 0; nt < 4; nt++) {
            const int cc = wn * 32 + nt * 8 + 2 * tig;
            const int ng = by * 128 + cc;
            const float b0 = bias[ng], b1 = bias[ng + 1];
#pragma unroll
            for (int half = 0; half < 2; half++) {
                const int m = m0 + wm * 64 + mt * 16 + gid + half * 8;
                float2 o;
                o.x = acc[mt][nt][half * 2 + 0] + b0;
                o.y = acc[mt][nt][half * 2 + 1] + b1;
                if (which != 3) {
                    const int nn = m >> 11;
                    const int kk = m & (K_ - 1);
                    const int h  = ng >> 6;
                    const int d  = ng & 63;
                    *(float2*)(proj_out + (((size_t)(nn * H_ + h) * K_ + kk) * D_ + d)) = o;
                } else {
                    *(float2*)(Cflat + (size_t)m * HD_ + ng) = o;
                }
            }
        }
    }
}

// ===========================================================================
// Flash attention on split-bf16 mma.
// grid (16 q-tiles of 128, 32 nh), block 256 (8 warps; warp w owns q-rows
// [16w,16w+16) -> softmax rows and P warp-local).
// QK: qh*kh + ql*kh + qh*kl.  PV: ph*vh + ph*vl + pl*vh.
// smem words: Kh/Kl[32 dp][72], Vh/Vl[32 jp][72], Ph/Pl[128][36]  = 18432
// ===========================================================================
#define KST 72
#define PST 36
#define QST 68
#define FLASH_SMEM (18432 * 4)

__global__ __launch_bounds__(256, 2) void flash_mma()
{
    extern __shared__ uint32_t sm[];
    uint32_t* Kh = sm;
    uint32_t* Kl = sm + 2304;
    uint32_t* Vh = sm + 4608;
    uint32_t* Vl = sm + 6912;
    uint32_t* Ph = sm + 9216;
    uint32_t* Pl = sm + 13824;
    uint32_t* Qst = sm + 9216;   // fp32 Q staging (consumed before P writes)

    const int qt = blockIdx.x, nh = blockIdx.y;
    const int n = nh >> 4, h = nh & 15;
    const int tid = threadIdx.x;
    const int w = tid >> 5, lane = tid & 31;
    const int gid = lane >> 2, tig = lane & 3;

    const float* Qg = g_q + ((size_t)nh * K_ + qt * 128) * D_;
    const float* Kg = g_k + (size_t)nh * K_ * D_;
    const float* Vg = g_v + (size_t)nh * K_ * D_;

    // ---- stage Q (fp32), then build persistent packed fragments ----
#pragma unroll
    for (int i = 0; i < 8; i++) {
        const int idx = tid + i * 256;
        const int row = idx >> 4, c4 = (idx & 15) << 2;
        float4 q = *(const float4*)(Qg + (size_t)row * D_ + c4);
        uint32_t* p = Qst + row * QST + c4;
        p[0] = __float_as_uint(q.x); p[1] = __float_as_uint(q.y);
        p[2] = __float_as_uint(q.z); p[3] = __float_as_uint(q.w);
    }
    __syncthreads();

    const int r0 = w * 16 + gid;
    uint32_t afh[4][4], afl[4][4];
#pragma unroll
    for (int sp = 0; sp < 4; sp++) {
        const int de = 16 * sp + 2 * tig;
#pragma unroll
        for (int u = 0; u < 4; u++) {
            const int row = r0 + (u & 1) * 8;
            const int col = de + (u >> 1) * 8;
            const float x0 = __uint_as_float(Qst[row * QST + col]);
            const float x1 = __uint_as_float(Qst[row * QST + col + 1]);
            bsplit(x0, x1, afh[sp][u], afl[sp][u]);
        }
    }

    float o[8][4] = {};
    float mrow[2] = { -FLT_MAX, -FLT_MAX };
    float lrow[2] = {};

    const uint32_t* mb0 = g_mb + (size_t)(n * K_ + qt * 128 + r0) * (K_ / 32);
    const uint32_t* mb1 = mb0 + 8 * (K_ / 32);

    for (int kt = 0; kt < 32; kt++) {
        __syncthreads();   // prior PV reads done; first iter: Q staging reads done

        // ---- load K (transpose + split, packed over d pairs) ----
        {
            const int j = tid & 63;
            const int db = tid >> 6;
#pragma unroll
            for (int i = 0; i < 4; i++) {
                const int d0 = (db + i * 4) << 2;
                float4 kx = *(const float4*)(Kg + (size_t)(kt * 64 + j) * D_ + d0);
                uint32_t h0, l0, h1, l1;
                bsplit(kx.x, kx.y, h0, l0);
                bsplit(kx.z, kx.w, h1, l1);
                const int dp = d0 >> 1;
                Kh[dp * KST + j] = h0; Kh[(dp + 1) * KST + j] = h1;
                Kl[dp * KST + j] = l0; Kl[(dp + 1) * KST + j] = l1;
            }
        }
        // ---- load V (split, packed over j pairs) ----
        {
            const int d4 = (tid & 15) << 2;
            const int jb = tid >> 4;
#pragma unroll
            for (int i = 0; i < 2; i++) {
                const int jp = jb + i * 16;
                const float* va = Vg + (size_t)(kt * 64 + 2 * jp) * D_ + d4;
                float4 v0 = *(const float4*)va;
                float4 v1 = *(const float4*)(va + D_);
                const float e0[4] = { v0.x, v0.y, v0.z, v0.w };
                const float e1[4] = { v1.x, v1.y, v1.z, v1.w };
                uint32_t hh[4], ll[4];
#pragma unroll
                for (int u = 0; u < 4; u++) bsplit(e0[u], e1[u], hh[u], ll[u]);
                *(uint4*)&Vh[jp * KST + d4] = make_uint4(hh[0], hh[1], hh[2], hh[3]);
                *(uint4*)&Vl[jp * KST + d4] = make_uint4(ll[0], ll[1], ll[2], ll[3]);
            }
        }
        __syncthreads();

        // ---- S = Q K^T ----
        float s[8][4] = {};
#pragma unroll
        for (int sp = 0; sp < 4; sp++) {
#pragma unroll
            for (int nt = 0; nt < 8; nt++) {
                const int i0 = (sp * 8 + tig) * KST + nt * 8 + gid;
                uint32_t bh[2] = { Kh[i0], Kh[i0 + 4 * KST] };
                uint32_t bl[2] = { Kl[i0], Kl[i0 + 4 * KST] };
                mma_bf16(s[nt], afh[sp], bh);
                mma_bf16(s[nt], afl[sp], bh);
                mma_bf16(s[nt], afh[sp], bl);
            }
        }

        // ---- mask + scale ----
        const uint2 m0 = *(const uint2*)(mb0 + kt * 2);
        const uint2 m1 = *(const uint2*)(mb1 + kt * 2);
#pragma unroll
        for (int nt = 0; nt < 8; nt++) {
            const int jb = nt * 8 + 2 * tig;
#pragma unroll
            for (int cc = 0; cc < 4; cc++) {
                const int j = jb + (cc & 1);
                const uint32_t word = (cc < 2) ? ((j < 32) ? m0.x : m0.y)
                                               : ((j < 32) ? m1.x : m1.y);
                const bool bit = (word >> (j & 31)) & 1u;
                s[nt][cc] = bit ? -1e9f : s[nt][cc] * 0.125f;
            }
        }

        // ---- online softmax (rows r0, r0+8) ----
        float mx0 = -FLT_MAX, mx1 = -FLT_MAX;
#pragma unroll
        for (int nt = 0; nt < 8; nt++) {
            mx0 = fmaxf(mx0, fmaxf(s[nt][0], s[nt][1]));
            mx1 = fmaxf(mx1, fmaxf(s[nt][2], s[nt][3]));
        }
        mx0 = fmaxf(mx0, __shfl_xor_sync(0xffffffffu, mx0, 1));
        mx0 = fmaxf(mx0, __shfl_xor_sync(0xffffffffu, mx0, 2));
        mx1 = fmaxf(mx1, __shfl_xor_sync(0xffffffffu, mx1, 1));
        mx1 = fmaxf(mx1, __shfl_xor_sync(0xffffffffu, mx1, 2));

        const float mn0 = fmaxf(mrow[0], mx0), mn1 = fmaxf(mrow[1], mx1);
        const float f0 = __expf(mrow[0] - mn0), f1 = __expf(mrow[1] - mn1);
        mrow[0] = mn0; mrow[1] = mn1;

        float sum0 = 0.f, sum1 = 0.f;
#pragma unroll
        for (int nt = 0; nt < 8; nt++) {
            s[nt][0] = __expf(s[nt][0] - mn0);
            s[nt][1] = __expf(s[nt][1] - mn0);
            s[nt][2] = __expf(s[nt][2] - mn1);
            s[nt][3] = __expf(s[nt][3] - mn1);
            sum0 += s[nt][0] + s[nt][1];
            sum1 += s[nt][2] + s[nt][3];
        }
        sum0 += __shfl_xor_sync(0xffffffffu, sum0, 1);
        sum0 += __shfl_xor_sync(0xffffffffu, sum0, 2);
        sum1 += __shfl_xor_sync(0xffffffffu, sum1, 1);
        sum1 += __shfl_xor_sync(0xffffffffu, sum1, 2);
        lrow[0] = lrow[0] * f0 + sum0;
        lrow[1] = lrow[1] * f1 + sum1;
#pragma unroll
        for (int dn = 0; dn < 8; dn++) {
            o[dn][0] *= f0; o[dn][1] *= f0;
            o[dn][2] *= f1; o[dn][3] *= f1;
        }

        // ---- write P split (warp-local rows) ----
#pragma unroll
        for (int nt = 0; nt < 8; nt++) {
            uint32_t hh, ll;
            bsplit(s[nt][0], s[nt][1], hh, ll);
            Ph[r0 * PST + nt * 4 + tig] = hh;
            Pl[r0 * PST + nt * 4 + tig] = ll;
            bsplit(s[nt][2], s[nt][3], hh, ll);
            Ph[(r0 + 8) * PST + nt * 4 + tig] = hh;
            Pl[(r0 + 8) * PST + nt * 4 + tig] = ll;
        }
        __syncwarp();

        // ---- O += P V ----
#pragma unroll
        for (int sp = 0; sp < 4; sp++) {
            uint32_t aph[4], apl[4];
            aph[0] = Ph[r0 * PST + sp * 8 + tig];
            aph[1] = Ph[(r0 + 8) * PST + sp * 8 + tig];
            aph[2] = Ph[r0 * PST + sp * 8 + tig + 4];
            aph[3] = Ph[(r0 + 8) * PST + sp * 8 + tig + 4];
            apl[0] = Pl[r0 * PST + sp * 8 + tig];
            apl[1] = Pl[(r0 + 8) * PST + sp * 8 + tig];
            apl[2] = Pl[r0 * PST + sp * 8 + tig + 4];
            apl[3] = Pl[(r0 + 8) * PST + sp * 8 + tig + 4];
#pragma unroll
            for (int dn = 0; dn < 8; dn++) {
                const int v0 = (sp * 8 + tig) * KST + dn * 8 + gid;
                uint32_t bh[2] = { Vh[v0], Vh[v0 + 4 * KST] };
                uint32_t bl[2] = { Vl[v0], Vl[v0 + 4 * KST] };
                mma_bf16(o[dn], aph, bh);
                mma_bf16(o[dn], aph, bl);
                mma_bf16(o[dn], apl, bh);
            }
        }
    }

    // ---- epilogue ----
    const float i0 = 1.0f / lrow[0], i1 = 1.0f / lrow[1];
    const size_t row0 = (size_t)n * K_ + qt * 128 + r0;
#pragma unroll
    for (int dn = 0; dn < 8; dn++) {
        const int col = h * 64 + dn * 8 + 2 * tig;
        *(float2*)(g_y + row0 * HD_ + col) =
            make_float2(o[dn][0] * i0, o[dn][1] * i0);
        *(float2*)(g_y + (row0 + 8) * HD_ + col) =
            make_float2(o[dn][2] * i1, o[dn][3] * i1);
    }
}

// ===========================================================================
extern "C" void kernel_launch(void* const* d_in, const int* in_sizes, int n_in,
                              void* d_out, int out_size)
{
    const float* query = (const float*)d_in[0];
    const float* key   = (const float*)d_in[1];
    const float* value = (const float*)d_in[2];
    const int*   mask  = (const int*)d_in[3];
    const float* Wq = (const float*)d_in[4];
    const float* bq = (const float*)d_in[5];
    const float* Wk = (const float*)d_in[6];
    const float* bk = (const float*)d_in[7];
    const float* Wv = (const float*)d_in[8];
    const float* bv = (const float*)d_in[9];
    const float* Wp = (const float*)d_in[10];
    const float* bp = (const float*)d_in[11];
    float* out = (float*)d_out;

    cudaFuncSetAttribute(gemm_mma, cudaFuncAttributeMaxDynamicSharedMemorySize, GEMM_SMEM);
    cudaFuncSetAttribute(flash_mma, cudaFuncAttributeMaxDynamicSharedMemorySize, FLASH_SMEM);

    mask_pack<<<(N_ * K_ * K_) / 256, 256>>>(mask);

    dim3 gg(32, 8), gb(256);
    gemm_mma<<<gg, gb, GEMM_SMEM>>>(query, Wq, bq, nullptr, 64, 63, 65536, 0);
    gemm_mma<<<gg, gb, GEMM_SMEM>>>(key,   Wk, bk, nullptr, 64, 63, 65536, 1);
    gemm_mma<<<gg, gb, GEMM_SMEM>>>(value, Wv, bv, nullptr, 64, 63, 65536, 2);

    dim3 gf(16, 32);
    flash_mma<<<gf, gb, FLASH_SMEM>>>();

    gemm_mma<<<gg, gb, GEMM_SMEM>>>(nullptr, Wp, bp, out, 1024, 1023, 0, 3);
}

// round 9
// speedup vs baseline: 2.9929x; 1.1202x over previous
#include <cuda_runtime.h>
#include <cstdint>
#include <float.h>

#define N_   2
#define K_   2048
#define DIN_ 1024
#define H_   16
#define D_   64
#define HD_  1024
#define QSCALE 0.18033688011112043f   // 0.125 * log2(e)

// ---------------- device scratch (allocation-free) ----------------
__device__ __align__(16) uint2    g_a [3][4096][512];     // split inputs (proj A)
__device__ __align__(16) uint2    g_wb[4][512][1024];     // split weights (B)
__device__ __align__(16) uint2    g_qp[32][2048][32];     // q plane (scaled), d-pair packed
__device__ __align__(16) uint2    g_kp[32][2048][32];     // k plane
__device__ __align__(16) uint32_t g_vh[32][64][1024];     // v hi  [nh][d][jpair]
__device__ __align__(16) uint32_t g_vl[32][64][1024];     // v lo
__device__ __align__(16) float    g_v [32][2048][64];     // v fp32 (n,h,k,d)
__device__ __align__(16) uint2    g_ya[4096][512];        // attention out, split (outproj A)
__device__ uint32_t g_mb[(size_t)N_ * K_ * 64];           // packed mask bits

// ---------------- helpers ----------------
__device__ __forceinline__ void bsplit(float x0, float x1, uint32_t& h, uint32_t& l) {
    const uint32_t u0 = __float_as_uint(x0), u1 = __float_as_uint(x1);
    h = __byte_perm(u0, u1, 0x7632);
    const float r0 = x0 - __uint_as_float(u0 & 0xffff0000u);
    const float r1 = x1 - __uint_as_float(u1 & 0xffff0000u);
    asm("cvt.rn.bf16x2.f32 %0, %1, %2;" : "=r"(l) : "f"(r1), "f"(r0));
}
__device__ __forceinline__ void mma_bf16(float* c, const uint32_t* a, const uint32_t* b) {
    asm volatile(
        "mma.sync.aligned.m16n8k16.row.col.f32.bf16.bf16.f32 "
        "{%0,%1,%2,%3}, {%4,%5,%6,%7}, {%8,%9}, {%0,%1,%2,%3};"
        : "+f"(c[0]), "+f"(c[1]), "+f"(c[2]), "+f"(c[3])
        : "r"(a[0]), "r"(a[1]), "r"(a[2]), "r"(a[3]), "r"(b[0]), "r"(b[1]));
}
__device__ __forceinline__ void ldm4(uint32_t* r, uint32_t addr) {
    asm volatile("ldmatrix.sync.aligned.m8n8.x4.shared.b16 {%0,%1,%2,%3}, [%4];"
                 : "=r"(r[0]), "=r"(r[1]), "=r"(r[2]), "=r"(r[3]) : "r"(addr));
}
__device__ __forceinline__ uint32_t smem_u32(const void* p) {
    uint32_t a;
    asm("{ .reg .u64 t; cvta.to.shared.u64 t, %1; cvt.u32.u64 %0, t; }" : "=r"(a) : "l"(p));
    return a;
}
__device__ __forceinline__ float ex2f(float x) {
    float r; asm("ex2.approx.f32 %0, %1;" : "=f"(r) : "f"(x)); return r;
}

// ---------------- prep kernels ----------------
__global__ __launch_bounds__(256) void mask_pack(const int* __restrict__ mask) {
    const int idx = blockIdx.x * 256 + threadIdx.x;
    const uint32_t b = __ballot_sync(0xffffffffu, mask[idx] != 0);
    if ((threadIdx.x & 31) == 0) g_mb[idx >> 5] = b;
}

__global__ __launch_bounds__(256) void split_a(const float* __restrict__ q,
    const float* __restrict__ k, const float* __restrict__ v) {
    const int z = blockIdx.y, row = blockIdx.x, c = threadIdx.x;
    const float* src = (z == 0) ? q : (z == 1) ? k : v;
    float4 x = *(const float4*)(src + (size_t)row * DIN_ + c * 4);
    uint32_t h0, l0, h1, l1;
    bsplit(x.x, x.y, h0, l0);
    bsplit(x.z, x.w, h1, l1);
    *(uint4*)&g_a[z][row][c * 2] = make_uint4(h0, l0, h1, l1);
}

__global__ __launch_bounds__(256) void split_w(const float* __restrict__ wq,
    const float* __restrict__ wk, const float* __restrict__ wv, const float* __restrict__ wp) {
    const int z = blockIdx.y, kp = blockIdx.x, ng = threadIdx.x * 4;
    float4 r0, r1;
    if (z < 3) {
        const float* s = (z == 0) ? wq : (z == 1) ? wk : wv;
        const size_t a0 = (size_t)(ng >> 6) * (DIN_ * D_) + (size_t)(2 * kp) * D_ + (ng & 63);
        r0 = *(const float4*)(s + a0);
        r1 = *(const float4*)(s + a0 + D_);
    } else {
        const size_t a0 = (size_t)(2 * kp) * DIN_ + ng;
        r0 = *(const float4*)(wp + a0);
        r1 = *(const float4*)(wp + a0 + DIN_);
    }
    uint32_t h[4], l[4];
    bsplit(r0.x, r1.x, h[0], l[0]);
    bsplit(r0.y, r1.y, h[1], l[1]);
    bsplit(r0.z, r1.z, h[2], l[2]);
    bsplit(r0.w, r1.w, h[3], l[3]);
    *(uint4*)&g_wb[z][kp][ng]     = make_uint4(h[0], l[0], h[1], l[1]);
    *(uint4*)&g_wb[z][kp][ng + 2] = make_uint4(h[2], l[2], h[3], l[3]);
}

// repack V: g_v fp32 -> token-pair packed planes g_vh/g_vl [nh][d][jp]
__global__ __launch_bounds__(256) void repack_v() {
    __shared__ float t[64][68];
    const int nh = blockIdx.y, jt = blockIdx.x, tid = threadIdx.x;
#pragma unroll
    for (int i = 0; i < 4; i++) {
        const int flat = tid + i * 256, tok = flat & 63, d4 = (flat >> 6) * 4;
        *(float4*)&t[tok][d4] = *(const float4*)&g_v[nh][jt * 64 + tok][d4];
    }
    __syncthreads();
    const int jp = tid & 31, dg = tid >> 5;
#pragma unroll
    for (int i = 0; i < 8; i++) {
        const int d = dg * 8 + i;
        uint32_t hh, ll;
        bsplit(t[2 * jp][d], t[2 * jp + 1][d], hh, ll);
        g_vh[nh][d][jt * 32 + jp] = hh;
        g_vl[nh][d][jt * 32 + jp] = ll;
    }
}

// ---------------- GEMM (pre-split operands, ldmatrix A frags) ----------------
// mode 0: grid (32,8,3)  A=g_a[z], B=g_wb[z]; out: z0->g_qp(scaled) z1->g_kp z2->g_v
// mode 1: grid (32,8,1)  A=g_ya,   B=g_wb[3]; out fp32
__global__ __launch_bounds__(256) void gemm_mma(int mode, const float* __restrict__ bq,
    const float* __restrict__ bk, const float* __restrict__ bv,
    const float* __restrict__ bp, float* __restrict__ outp)
{
    __shared__ uint32_t gsm[10496];
    const uint32_t sb = smem_u32(gsm);

    const int tid = threadIdx.x, wid = tid >> 5, lane = tid & 31;
    const int gid = lane >> 2, tig = lane & 3, wm = wid >> 2, wn = wid & 3;
    const int m0 = blockIdx.x * 128, by = blockIdx.y;
    const int z = (mode == 0) ? blockIdx.z : 3;

    const uint2* A  = (mode == 0) ? &g_a[z][0][0] : &g_ya[0][0];
    const uint2* Bw = &g_wb[z][0][0];
    const float* bias = (z == 0) ? bq : (z == 1) ? bk : (z == 2) ? bv : bp;

    const int am = tid >> 2, akg = tid & 3;           // A loader
    const int bkp = tid >> 5, bn4 = (tid & 31) << 2;  // B loader
    const int bcol = by * 128 + bn4;                  // B global column (FIX)
    float acc[4][4][4] = {};
    uint4 avv[2], bv0, bv1;

#define AW(b,hl) (((b)*2+(hl))*1536)
#define BW(b,hl) (6144 + ((b)*2+(hl))*1088)

    // prologue chunk 0
#pragma unroll
    for (int i = 0; i < 2; i++)
        avv[i] = *(const uint4*)&A[(size_t)(m0 + am + i * 64) * 512 + akg * 2];
    bv0 = *(const uint4*)&Bw[(size_t)bkp * 1024 + bcol];
    bv1 = *(const uint4*)&Bw[(size_t)bkp * 1024 + bcol + 2];
#pragma unroll
    for (int i = 0; i < 2; i++) {
        const int r = am + i * 64;
        *(uint2*)&gsm[AW(0,0) + r * 12 + akg * 2] = make_uint2(avv[i].x, avv[i].z);
        *(uint2*)&gsm[AW(0,1) + r * 12 + akg * 2] = make_uint2(avv[i].y, avv[i].w);
    }
    *(uint4*)&gsm[BW(0,0) + bkp * 136 + bn4] = make_uint4(bv0.x, bv0.z, bv1.x, bv1.z);
    *(uint4*)&gsm[BW(0,1) + bkp * 136 + bn4] = make_uint4(bv0.y, bv0.w, bv1.y, bv1.w);
    __syncthreads();

    for (int c = 0; c < 64; c++) {
        const int buf = c & 1;
        if (c < 63) {
            const int kp0 = (c + 1) * 8;   // kpair units (FIX: no *2)
#pragma unroll
            for (int i = 0; i < 2; i++)
                avv[i] = *(const uint4*)&A[(size_t)(m0 + am + i * 64) * 512 + kp0 + akg * 2];
            bv0 = *(const uint4*)&Bw[(size_t)(kp0 + bkp) * 1024 + bcol];
            bv1 = *(const uint4*)&Bw[(size_t)(kp0 + bkp) * 1024 + bcol + 2];
        }
        uint32_t ah[4][4], al[4][4];
#pragma unroll
        for (int mt = 0; mt < 4; mt++) {
            const uint32_t r = wm * 64 + mt * 16 + (lane & 15);
            const uint32_t off = r * 12 + (lane >> 4) * 4;
            ldm4(ah[mt], sb + (AW(buf,0) + off) * 4);
            ldm4(al[mt], sb + (AW(buf,1) + off) * 4);
        }
        uint32_t bh[4][2], bl[4][2];
#pragma unroll
        for (int nt = 0; nt < 4; nt++) {
            const int nc = wn * 32 + nt * 8 + gid;
            bh[nt][0] = gsm[BW(buf,0) + tig * 136 + nc];
            bh[nt][1] = gsm[BW(buf,0) + (tig + 4) * 136 + nc];
            bl[nt][0] = gsm[BW(buf,1) + tig * 136 + nc];
            bl[nt][1] = gsm[BW(buf,1) + (tig + 4) * 136 + nc];
        }
#pragma unroll
        for (int mt = 0; mt < 4; mt++)
#pragma unroll
            for (int nt = 0; nt < 4; nt++) {
                mma_bf16(acc[mt][nt], ah[mt], bh[nt]);
                mma_bf16(acc[mt][nt], al[mt], bh[nt]);
                mma_bf16(acc[mt][nt], ah[mt], bl[nt]);
            }
        if (c < 63) {
            const int nb = buf ^ 1;
#pragma unroll
            for (int i = 0; i < 2; i++) {
                const int r = am + i * 64;
                *(uint2*)&gsm[AW(nb,0) + r * 12 + akg * 2] = make_uint2(avv[i].x, avv[i].z);
                *(uint2*)&gsm[AW(nb,1) + r * 12 + akg * 2] = make_uint2(avv[i].y, avv[i].w);
            }
            *(uint4*)&gsm[BW(nb,0) + bkp * 136 + bn4] = make_uint4(bv0.x, bv0.z, bv1.x, bv1.z);
            *(uint4*)&gsm[BW(nb,1) + bkp * 136 + bn4] = make_uint4(bv0.y, bv0.w, bv1.y, bv1.w);
            __syncthreads();
        }
    }

    // epilogue
#pragma unroll
    for (int mt = 0; mt < 4; mt++)
#pragma unroll
        for (int nt = 0; nt < 4; nt++) {
            const int ng = by * 128 + wn * 32 + nt * 8 + 2 * tig;
            const float b0 = bias[ng], b1 = bias[ng + 1];
#pragma unroll
            for (int half = 0; half < 2; half++) {
                const int m = m0 + wm * 64 + mt * 16 + gid + half * 8;
                float v0 = acc[mt][nt][half * 2 + 0] + b0;
                float v1 = acc[mt][nt][half * 2 + 1] + b1;
                if (mode == 1) {
                    *(float2*)(outp + (size_t)m * HD_ + ng) = make_float2(v0, v1);
                } else {
                    const int nn = m >> 11, kk = m & 2047, h = ng >> 6;
                    if (z == 2) {
                        *(float2*)&g_v[nn * 16 + h][kk][ng & 63] = make_float2(v0, v1);
                    } else {
                        if (z == 0) { v0 *= QSCALE; v1 *= QSCALE; }
                        uint32_t hh, ll;
                        bsplit(v0, v1, hh, ll);
                        ((z == 0) ? g_qp : g_kp)[nn * 16 + h][kk][(ng >> 1) & 31] = make_uint2(hh, ll);
                    }
                }
            }
        }
}

// ---------------- flash attention ----------------
// grid (16 q-tiles of 128, 32 nh), block 256. Warp w owns q rows [16w,16w+16).
// smem 9216 words: phase1 Qh[128][36]@0, Ql@4608; phase2 Kh@0,Kl@2304,Vh@4608,Vl@6912
__global__ __launch_bounds__(256, 2) void flash_mma()
{
    __shared__ uint32_t sm[9216];
    const uint32_t sb = smem_u32(sm);

    const int qt = blockIdx.x, nh = blockIdx.y, n = nh >> 4, h = nh & 15;
    const int tid = threadIdx.x, w = tid >> 5, lane = tid & 31;
    const int gid = lane >> 2, tig = lane & 3, r0 = w * 16 + gid;

    // stage Q planes, build persistent frags
    {
        const int row = tid >> 1, hf = tid & 1;
        const uint2* src = &g_qp[nh][qt * 128 + row][hf * 16];
        uint32_t* qh = sm + row * 36 + hf * 16;
        uint32_t* ql = sm + 4608 + row * 36 + hf * 16;
#pragma unroll
        for (int i = 0; i < 4; i++) {
            uint4 a = *(const uint4*)(src + i * 4);
            uint4 b = *(const uint4*)(src + i * 4 + 2);
            *(uint4*)(qh + i * 4) = make_uint4(a.x, a.z, b.x, b.z);
            *(uint4*)(ql + i * 4) = make_uint4(a.y, a.w, b.y, b.w);
        }
    }
    __syncthreads();
    uint32_t afh[4][4], afl[4][4];
    {
        const uint32_t off = (uint32_t)(w * 16 + (lane & 15)) * 36 + (lane >> 4) * 4;
#pragma unroll
        for (int sp = 0; sp < 4; sp++) {
            ldm4(afh[sp], sb + (off + sp * 8) * 4);
            ldm4(afl[sp], sb + (4608 + off + sp * 8) * 4);
        }
    }

    float o[8][4] = {};
    float ls0 = 0.f, ls1 = 0.f;
    const uint32_t* mr0 = g_mb + (size_t)(n * K_ + qt * 128 + r0) * 64;
    const uint32_t* mr1 = mr0 + 8 * 64;

    const uint32_t brow = (lane & 7) + ((lane & 16) ? 8u : 0u);
    const uint32_t bbyt = (lane & 8) ? 16u : 0u;

    for (int kt = 0; kt < 32; kt++) {
        __syncthreads();
        // load K plane tile -> [j][dp]
        {
            const int j = tid >> 2, wg = tid & 3;
            const uint2* src = &g_kp[nh][kt * 64 + j][wg * 8];
            uint4 a = *(const uint4*)(src);
            uint4 b = *(const uint4*)(src + 2);
            uint4 c = *(const uint4*)(src + 4);
            uint4 d = *(const uint4*)(src + 6);
            uint32_t* kh = sm + j * 36 + wg * 8;
            *(uint4*)(kh)     = make_uint4(a.x, a.z, b.x, b.z);
            *(uint4*)(kh + 4) = make_uint4(c.x, c.z, d.x, d.z);
            uint32_t* kl = sm + 2304 + j * 36 + wg * 8;
            *(uint4*)(kl)     = make_uint4(a.y, a.w, b.y, b.w);
            *(uint4*)(kl + 4) = make_uint4(c.y, c.w, d.y, d.w);
        }
        // load V planes tile -> [d][jp]
        {
            const int d = tid >> 2, wg = tid & 3;
            *(uint4*)(sm + 4608 + d * 36 + wg * 8) =
                *(const uint4*)&g_vh[nh][d][kt * 32 + wg * 8];
            *(uint4*)(sm + 4608 + d * 36 + wg * 8 + 4) =
                *(const uint4*)&g_vh[nh][d][kt * 32 + wg * 8 + 4];
            *(uint4*)(sm + 6912 + d * 36 + wg * 8) =
                *(const uint4*)&g_vl[nh][d][kt * 32 + wg * 8];
            *(uint4*)(sm + 6912 + d * 36 + wg * 8 + 4) =
                *(const uint4*)&g_vl[nh][d][kt * 32 + wg * 8 + 4];
        }
        __syncthreads();

        // S = Q K^T (3-term)
        float s[8][4] = {};
#pragma unroll
        for (int sp = 0; sp < 4; sp++) {
#pragma unroll
            for (int g = 0; g < 4; g++) {
                const uint32_t base = ((g * 16 + brow) * 36 + sp * 8) * 4 + bbyt;
                uint32_t kh4[4], kl4[4];
                ldm4(kh4, sb + base);
                ldm4(kl4, sb + 2304 * 4 + base);
#pragma unroll
                for (int t = 0; t < 2; t++) {
                    mma_bf16(s[g * 2 + t], afh[sp], kh4 + 2 * t);
                    mma_bf16(s[g * 2 + t], afl[sp], kh4 + 2 * t);
                    mma_bf16(s[g * 2 + t], afh[sp], kl4 + 2 * t);
                }
            }
        }

        // mask + exp2 (no-max softmax; scale folded into q)
        const uint2 w0 = *(const uint2*)(mr0 + kt * 2);
        const uint2 w1 = *(const uint2*)(mr1 + kt * 2);
#pragma unroll
        for (int nt = 0; nt < 8; nt++) {
            const int jb = nt * 8 + 2 * tig;
#pragma unroll
            for (int cc = 0; cc < 4; cc++) {
                const int j = jb + (cc & 1);
                const uint32_t word = (cc < 2) ? ((j < 32) ? w0.x : w0.y)
                                               : ((j < 32) ? w1.x : w1.y);
                s[nt][cc] = ((word >> (j & 31)) & 1u) ? 0.f : ex2f(s[nt][cc]);
            }
            ls0 += s[nt][0] + s[nt][1];
            ls1 += s[nt][2] + s[nt][3];
        }

        // O += P V (P frags built in registers)
#pragma unroll
        for (int sp = 0; sp < 4; sp++) {
            uint32_t aph[4], apl[4];
            bsplit(s[2 * sp][0],     s[2 * sp][1],     aph[0], apl[0]);
            bsplit(s[2 * sp][2],     s[2 * sp][3],     aph[1], apl[1]);
            bsplit(s[2 * sp + 1][0], s[2 * sp + 1][1], aph[2], apl[2]);
            bsplit(s[2 * sp + 1][2], s[2 * sp + 1][3], aph[3], apl[3]);
#pragma unroll
            for (int g = 0; g < 4; g++) {
                const uint32_t base = ((g * 16 + brow) * 36 + sp * 8) * 4 + bbyt;
                uint32_t vh4[4], vl4[4];
                ldm4(vh4, sb + 4608 * 4 + base);
                ldm4(vl4, sb + 6912 * 4 + base);
#pragma unroll
                for (int t = 0; t < 2; t++) {
                    mma_bf16(o[g * 2 + t], aph, vh4 + 2 * t);
                    mma_bf16(o[g * 2 + t], apl, vh4 + 2 * t);
                    mma_bf16(o[g * 2 + t], aph, vl4 + 2 * t);
                }
            }
        }
    }

    // epilogue: row sums, normalize, write split outproj-A
    ls0 += __shfl_xor_sync(0xffffffffu, ls0, 1);
    ls0 += __shfl_xor_sync(0xffffffffu, ls0, 2);
    ls1 += __shfl_xor_sync(0xffffffffu, ls1, 1);
    ls1 += __shfl_xor_sync(0xffffffffu, ls1, 2);
    const float i0 = 1.0f / ls0, i1 = 1.0f / ls1;
    const int row = n * K_ + qt * 128 + r0;
#pragma unroll
    for (int dn = 0; dn < 8; dn++) {
        const int dp = h * 32 + dn * 4 + tig;
        uint32_t hh, ll;
        bsplit(o[dn][0] * i0, o[dn][1] * i0, hh, ll);
        g_ya[row][dp] = make_uint2(hh, ll);
        bsplit(o[dn][2] * i1, o[dn][3] * i1, hh, ll);
        g_ya[row + 8][dp] = make_uint2(hh, ll);
    }
}

// ---------------- launch ----------------
extern "C" void kernel_launch(void* const* d_in, const int* in_sizes, int n_in,
                              void* d_out, int out_size)
{
    const float* query = (const float*)d_in[0];
    const float* key   = (const float*)d_in[1];
    const float* value = (const float*)d_in[2];
    const int*   mask  = (const int*)d_in[3];
    const float* Wq = (const float*)d_in[4];
    const float* bq = (const float*)d_in[5];
    const float* Wk = (const float*)d_in[6];
    const float* bk = (const float*)d_in[7];
    const float* Wv = (const float*)d_in[8];
    const float* bv = (const float*)d_in[9];
    const float* Wp = (const float*)d_in[10];
    const float* bp = (const float*)d_in[11];
    float* out = (float*)d_out;

    mask_pack<<<(N_ * K_ * K_) / 256, 256>>>(mask);
    split_a<<<dim3(4096, 3), 256>>>(query, key, value);
    split_w<<<dim3(512, 4), 256>>>(Wq, Wk, Wv, Wp);
    gemm_mma<<<dim3(32, 8, 3), 256>>>(0, bq, bk, bv, bp, nullptr);
    repack_v<<<dim3(32, 32), 256>>>();
    flash_mma<<<dim3(16, 32), 256>>>();
    gemm_mma<<<dim3(32, 8, 1), 256>>>(1, bq, bk, bv, bp, out);
}